// round 13
// baseline (speedup 1.0000x reference)
#include <cuda_runtime.h>
#include <cuda_fp16.h>
#include <cstdint>

#define SEQ   2048
#define DM    2048
#define NH    32
#define DH    64
#define CK    128
#define NC    16
#define BZ    4
#define MROWS (BZ*SEQ)   // 8192
#define BK    16
#define NKT   (DM/BK)    // 128

// ---------------- scratch (device globals; no allocation) ----------------
__device__ __align__(256) __half g_rxh [BZ*SEQ*DM];
__device__ __align__(256) __half g_kxh [BZ*SEQ*DM];
__device__ __align__(256) __half g_vxh [BZ*SEQ*DM];
__device__ __align__(256) __half g_atth[BZ*SEQ*DM];
__device__ float g_r  [BZ*SEQ*DM];
__device__ float g_k  [BZ*SEQ*DM];
__device__ float g_v  [BZ*SEQ*DM];
__device__ float g_att[BZ*SEQ*DM];
__device__ float g_kv   [BZ*NH*NC*DH*DH];
__device__ float g_state[BZ*NH*NC*DH*DH];
__device__ __align__(256) __half g_wtr[DM*DM];
__device__ __align__(256) __half g_wtk[DM*DM];
__device__ __align__(256) __half g_wtv[DM*DM];
__device__ __align__(256) __half g_wto[DM*DM];

// ---------------- small PTX helpers ----------------
__device__ __forceinline__ uint32_t smem_u32(const void* p)
{
    uint32_t a;
    asm("{ .reg .u64 t; cvta.to.shared.u64 t, %1; cvt.u32.u64 %0, t; }" : "=r"(a) : "l"(p));
    return a;
}
template<int N> __device__ __forceinline__ void cp_wait()
{
    asm volatile("cp.async.wait_group %0;" :: "n"(N) : "memory");
}
__device__ __forceinline__ void cp16(uint32_t dst, const void* src)
{
    asm volatile("cp.async.cg.shared.global [%0], [%1], 16;" :: "r"(dst), "l"(src));
}
__device__ __forceinline__ void cp_commit()
{
    asm volatile("cp.async.commit_group;" ::: "memory");
}
__device__ __forceinline__ void mma_f16(float* c, const unsigned* a, const unsigned* b)
{
    asm volatile(
        "mma.sync.aligned.m16n8k16.row.col.f32.f16.f16.f32 "
        "{%0,%1,%2,%3}, {%4,%5,%6,%7}, {%8,%9}, {%0,%1,%2,%3};"
        : "+f"(c[0]), "+f"(c[1]), "+f"(c[2]), "+f"(c[3])
        : "r"(a[0]), "r"(a[1]), "r"(a[2]), "r"(a[3]),
          "r"(b[0]), "r"(b[1]));
}
__device__ __forceinline__ void ldsm4(unsigned* r, uint32_t addr)
{
    asm volatile("ldmatrix.sync.aligned.m8n8.x4.shared.b16 {%0,%1,%2,%3}, [%4];"
        : "=r"(r[0]), "=r"(r[1]), "=r"(r[2]), "=r"(r[3]) : "r"(addr));
}
__device__ __forceinline__ void ldsm4t(unsigned* r, uint32_t addr)
{
    asm volatile("ldmatrix.sync.aligned.m8n8.x4.trans.shared.b16 {%0,%1,%2,%3}, [%4];"
        : "=r"(r[0]), "=r"(r[1]), "=r"(r[2]), "=r"(r[3]) : "r"(addr));
}

// ---------------- fused LN + token-shift mixing (fp16 outputs) ------------
__global__ void lnmix_kernel(const float* __restrict__ x,
                             const float* __restrict__ sc,
                             const float* __restrict__ bi,
                             const float* __restrict__ tmr,
                             const float* __restrict__ tmk,
                             const float* __restrict__ tmv,
                             float* __restrict__ xlast)
{
    int row = blockIdx.x;
    int t   = row & (SEQ - 1);
    const float* xr = x + (size_t)row * DM;
    float cur[8], prv[8];
    float s0 = 0.f, q0 = 0.f, s1 = 0.f, q1 = 0.f;
#pragma unroll
    for (int i = 0; i < 8; i++) {
        int c = threadIdx.x + i * 256;
        float v = xr[c];
        cur[i] = v; s0 += v; q0 += v * v;
        float u = t ? xr[c - DM] : 0.f;
        prv[i] = u; s1 += u; q1 += u * u;
    }
#pragma unroll
    for (int o = 16; o > 0; o >>= 1) {
        s0 += __shfl_xor_sync(0xffffffffu, s0, o);
        q0 += __shfl_xor_sync(0xffffffffu, q0, o);
        s1 += __shfl_xor_sync(0xffffffffu, s1, o);
        q1 += __shfl_xor_sync(0xffffffffu, q1, o);
    }
    __shared__ float rs0[8], rq0[8], rs1[8], rq1[8];
    int w = threadIdx.x >> 5;
    if ((threadIdx.x & 31) == 0) { rs0[w] = s0; rq0[w] = q0; rs1[w] = s1; rq1[w] = q1; }
    __syncthreads();
    s0 = 0.f; q0 = 0.f; s1 = 0.f; q1 = 0.f;
#pragma unroll
    for (int i = 0; i < 8; i++) { s0 += rs0[i]; q0 += rq0[i]; s1 += rs1[i]; q1 += rq1[i]; }
    float mu0  = s0 * (1.f / DM);
    float inv0 = rsqrtf(q0 * (1.f / DM) - mu0 * mu0 + 1e-5f);
    float mu1  = s1 * (1.f / DM);
    float inv1 = rsqrtf(q1 * (1.f / DM) - mu1 * mu1 + 1e-5f);
    bool last = (t == SEQ - 1);
#pragma unroll
    for (int i = 0; i < 8; i++) {
        int c = threadIdx.x + i * 256;
        float yc = (cur[i] - mu0) * inv0 * sc[c] + bi[c];
        float yp = t ? (prv[i] - mu1) * inv1 * sc[c] + bi[c] : 0.f;
        size_t off = (size_t)row * DM + c;
        float mr = tmr[c], mk = tmk[c], mv = tmv[c];
        g_rxh[off] = __float2half(yc * mr + (1.f - mr) * yp);
        g_kxh[off] = __float2half(yc * mk + (1.f - mk) * yp);
        g_vxh[off] = __float2half(yc * mv + (1.f - mv) * yp);
        if (last) xlast[(row >> 11) * DM + c] = yc;
    }
}

// ---------------- 4 weight transposes in one launch (fp16 outputs) --------
__global__ void transpose4_kernel(const float* __restrict__ s0, __half* __restrict__ d0,
                                  const float* __restrict__ s1, __half* __restrict__ d1,
                                  const float* __restrict__ s2, __half* __restrict__ d2,
                                  const float* __restrict__ s3, __half* __restrict__ d3)
{
    const float* src; __half* dst;
    switch (blockIdx.z) {
        case 0:  src = s0; dst = d0; break;
        case 1:  src = s1; dst = d1; break;
        case 2:  src = s2; dst = d2; break;
        default: src = s3; dst = d3; break;
    }
    __shared__ float t[32][33];
    int bx = blockIdx.x * 32, by = blockIdx.y * 32;
#pragma unroll
    for (int i = 0; i < 4; i++)
        t[threadIdx.y + i * 8][threadIdx.x] =
            src[(size_t)(by + threadIdx.y + i * 8) * DM + bx + threadIdx.x];
    __syncthreads();
#pragma unroll
    for (int i = 0; i < 4; i++)
        dst[(size_t)(bx + threadIdx.y + i * 8) * DM + by + threadIdx.x] =
            __float2half(t[threadIdx.x][threadIdx.y + i * 8]);
}

// ---------------- fp16 mma.sync GEMM, cp.async 4-stage, ldmatrix ----------
// Separate launches per GEMM (z-fusion rejected: L2 weight-reuse loss, R6+R12)
#define HSTRIDE 24                        // halves per smem row (16 data + 8 pad)
#define STG_BYTES (2 * 128 * HSTRIDE * 2) // A tile + B tile per stage = 12288 B

template<int MODE>
__global__ void __launch_bounds__(256, 2) tgemm_kernel(const __half* __restrict__ Bt,
                                                       const float* __restrict__ Add,
                                                       float* __restrict__ Out)
{
    const __half* A;
    float* C;
    if constexpr (MODE == 0) { A = g_rxh; C = g_r; }
    else if constexpr (MODE == 1) { A = g_kxh; C = g_k; }
    else if constexpr (MODE == 2) { A = g_vxh; C = g_v; }
    else { A = g_atth; C = Out; }

    extern __shared__ char smem[];
    uint32_t sb = smem_u32(smem);
    int tid = threadIdx.x, lane = tid & 31, warp = tid >> 5;
    int r0 = lane >> 2, c0 = lane & 3;
    int wm = (warp >> 2) * 64, wn = (warp & 3) * 32;
    int bm = blockIdx.y * 128, bn = blockIdx.x * 128;

    const __half* Ag = A  + (size_t)bm * DM;
    const __half* Bg = Bt + (size_t)bn * DM;

    int lane7 = lane & 7;
    uint32_t a_off = (uint32_t)(((wm + ((lane >> 3) & 1) * 8 + lane7) * HSTRIDE
                                + ((lane >> 4) & 1) * 8) * 2);
    uint32_t b_off = (uint32_t)(((wn + ((lane >> 4) & 1) * 8 + lane7) * HSTRIDE
                                + ((lane >> 3) & 1) * 8) * 2);

    // copy: one thread per row (0-127 -> A rows, 128-255 -> B rows).
    // STS 16B-phase = 3*row mod 8 over 8-lane groups -> conflict-free
    int crow = tid & 127;
    const __half* cbase = (tid < 128) ? Ag : Bg;
    uint32_t cdst = (tid < 128) ? 0u : (uint32_t)(128 * HSTRIDE * 2);
    auto copy_stage = [&](int buf, int kt) {
        uint32_t s = sb + buf * STG_BYTES + cdst + crow * (HSTRIDE * 2);
        const __half* src = cbase + kt * BK + (size_t)crow * DM;
        cp16(s,      src);
        cp16(s + 16, src + 8);
        cp_commit();
    };

    float acc[4][4][4];
#pragma unroll
    for (int i = 0; i < 4; i++)
#pragma unroll
        for (int j = 0; j < 4; j++)
#pragma unroll
            for (int e = 0; e < 4; e++) acc[i][j][e] = 0.f;

    copy_stage(0, 0);
    copy_stage(1, 1);
    copy_stage(2, 2);
    cp_wait<2>();
    __syncthreads();

    for (int kt = 0; kt < NKT; kt++) {
        int buf = kt & 3;
        uint32_t sA = sb + buf * STG_BYTES;
        uint32_t sB = sA + 128 * HSTRIDE * 2;
        unsigned af[4][4], bf[8];
#pragma unroll
        for (int i = 0; i < 4; i++)
            ldsm4(af[i], sA + a_off + i * (16 * HSTRIDE * 2));
        ldsm4(&bf[0], sB + b_off);
        ldsm4(&bf[4], sB + b_off + 16 * HSTRIDE * 2);
#pragma unroll
        for (int i = 0; i < 4; i++)
#pragma unroll
            for (int j = 0; j < 4; j++)
                mma_f16(acc[i][j], af[i], &bf[j * 2]);
        // one commit-group per iteration (empty in tail) keeps wait<2>'s
        // "next tile resident" invariant
        if (kt + 3 < NKT) copy_stage((kt + 3) & 3, kt + 3);
        else              cp_commit();
        cp_wait<2>();
        __syncthreads();
    }

#pragma unroll
    for (int i = 0; i < 4; i++) {
        int row = bm + wm + i * 16 + r0;
#pragma unroll
        for (int j = 0; j < 4; j++) {
            int col = bn + wn + j * 8 + c0 * 2;
            size_t o0 = (size_t)row * DM + col;
            size_t o1 = (size_t)(row + 8) * DM + col;
            float2 v0 = make_float2(acc[i][j][0], acc[i][j][1]);
            float2 v1 = make_float2(acc[i][j][2], acc[i][j][3]);
            if constexpr (MODE == 3) {
                float2 a0 = *(const float2*)(Add + o0);
                float2 a1 = *(const float2*)(Add + o1);
                v0.x += a0.x; v0.y += a0.y;
                v1.x += a1.x; v1.y += a1.y;
            }
            *(float2*)(C + o0) = v0;
            *(float2*)(C + o1) = v1;
        }
    }
}

// ---------------- fused attention: sep = ((r@k^T)*mask) @ v ---------------
#define RSTR 72    // halves per row, r/k/v tiles (64 data + 8 pad)
#define SSTR 136   // halves per row, S tile (128 data + 8 pad)
#define ATT_SMEM (3 * 128 * RSTR * 2 + 128 * SSTR * 2)   // 90112 B

__global__ void __launch_bounds__(256, 2) att_kernel(const float* __restrict__ tdcy,
                                                     const float* __restrict__ tfirst)
{
    int bch = blockIdx.x;
    int h = bch & 31;
    int chunk = (bch >> 5) & 15;
    int b = bch >> 9;
    extern __shared__ char smem[];
    __half* rs = (__half*)smem;
    __half* ks = rs + 128 * RSTR;
    __half* vs = ks + 128 * RSTR;
    __half* ss = vs + 128 * RSTR;
    int tid = threadIdx.x, lane = tid & 31, warp = tid >> 5;
    int lane7 = lane & 7;
    int r0 = lane >> 2, c0 = lane & 3;

    size_t gbase = ((size_t)(b * SEQ + chunk * CK)) * DM + h * 64;
#pragma unroll
    for (int q = 0; q < 8; q++) {
        int idx = q * 256 + tid;
        int row = idx >> 4, cc = (idx & 15) * 4;
        size_t off = gbase + (size_t)row * DM + cc;
        float4 rv = *(const float4*)(g_r + off);
        float4 kv = *(const float4*)(g_k + off);
        float4 vv = *(const float4*)(g_v + off);
        __half2* rp = (__half2*)&rs[row * RSTR + cc];
        rp[0] = __floats2half2_rn(rv.x, rv.y); rp[1] = __floats2half2_rn(rv.z, rv.w);
        __half2* kp = (__half2*)&ks[row * RSTR + cc];
        kp[0] = __floats2half2_rn(kv.x, kv.y); kp[1] = __floats2half2_rn(kv.z, kv.w);
        __half2* vp = (__half2*)&vs[row * RSTR + cc];
        vp[0] = __floats2half2_rn(vv.x, vv.y); vp[1] = __floats2half2_rn(vv.z, vv.w);
    }
    __syncthreads();

    int wm = (warp >> 2) * 64, wn = (warp & 3) * 32;
    uint32_t rs_b = smem_u32(rs), ks_b = smem_u32(ks);
    uint32_t vs_b = smem_u32(vs), ss_b = smem_u32(ss);
    uint32_t a_off = rs_b + (uint32_t)(((wm + ((lane >> 3) & 1) * 8 + lane7) * RSTR
                                      + ((lane >> 4) & 1) * 8) * 2);
    uint32_t b_off = ks_b + (uint32_t)(((wn + ((lane >> 4) & 1) * 8 + lane7) * RSTR
                                      + ((lane >> 3) & 1) * 8) * 2);
    float acc[4][4][4];
#pragma unroll
    for (int i = 0; i < 4; i++)
#pragma unroll
        for (int j = 0; j < 4; j++)
#pragma unroll
            for (int e = 0; e < 4; e++) acc[i][j][e] = 0.f;
#pragma unroll
    for (int kb = 0; kb < 4; kb++) {
        unsigned af[4][4], bf[8];
#pragma unroll
        for (int i = 0; i < 4; i++)
            ldsm4(af[i], a_off + i * (16 * RSTR * 2) + kb * 32);
        ldsm4(&bf[0], b_off + kb * 32);
        ldsm4(&bf[4], b_off + 16 * RSTR * 2 + kb * 32);
#pragma unroll
        for (int i = 0; i < 4; i++)
#pragma unroll
            for (int j = 0; j < 4; j++)
                mma_f16(acc[i][j], af[i], &bf[j * 2]);
    }

    float logw = -expf(tdcy[h]);
    float u    =  expf(tfirst[h]);
#pragma unroll
    for (int i = 0; i < 4; i++) {
#pragma unroll
        for (int j = 0; j < 4; j++) {
            int ri = wm + i * 16 + r0;
            int cj = wn + j * 8 + c0 * 2;
#pragma unroll
            for (int e = 0; e < 4; e++) {
                int rr = ri + (e >> 1) * 8;
                int cc = cj + (e & 1);
                float m;
                if (rr > cc)       m = expf(logw * (float)(rr - cc - 1));
                else if (rr == cc) m = u;
                else               m = 0.f;
                ss[rr * SSTR + cc] = __float2half(acc[i][j][e] * m);
            }
        }
    }
    __syncthreads();

    int wm2 = (warp >> 2) * 64, wn2 = (warp & 3) * 16;
    uint32_t a2 = ss_b + (uint32_t)(((wm2 + ((lane >> 3) & 1) * 8 + lane7) * SSTR
                                   + ((lane >> 4) & 1) * 8) * 2);
    uint32_t bt = vs_b + (uint32_t)(((((lane >> 3) & 1) * 8 + lane7) * RSTR
                                   + wn2 + ((lane >> 4) & 1) * 8) * 2);
    float acc2[4][2][4];
#pragma unroll
    for (int i = 0; i < 4; i++)
#pragma unroll
        for (int j = 0; j < 2; j++)
#pragma unroll
            for (int e = 0; e < 4; e++) acc2[i][j][e] = 0.f;
#pragma unroll
    for (int kb = 0; kb < 8; kb++) {
        unsigned af[4][4], bf[4];
#pragma unroll
        for (int i = 0; i < 4; i++)
            ldsm4(af[i], a2 + i * (16 * SSTR * 2) + kb * 32);
        ldsm4t(bf, bt + kb * (16 * RSTR * 2));
#pragma unroll
        for (int i = 0; i < 4; i++)
#pragma unroll
            for (int j = 0; j < 2; j++)
                mma_f16(acc2[i][j], af[i], &bf[j * 2]);
    }
#pragma unroll
    for (int i = 0; i < 4; i++) {
        int row = wm2 + i * 16 + r0;
        size_t o = ((size_t)(b * SEQ + chunk * CK + row)) * DM + h * 64;
#pragma unroll
        for (int j = 0; j < 2; j++) {
            int col = wn2 + j * 8 + c0 * 2;
            *(float2*)(g_att + o + col) = make_float2(acc2[i][j][0], acc2[i][j][1]);
            *(float2*)(g_att + o + (size_t)8 * DM + col) = make_float2(acc2[i][j][2], acc2[i][j][3]);
        }
    }
}

// ---------------- scan decomposition ----------------
__global__ void kv_kernel(const float* __restrict__ tdcy)
{
    int c = blockIdx.x, bh = blockIdx.y;
    int h = bh & 31, b = bh >> 5;
    int tid = threadIdx.x;
    __shared__ float bufA[32][68];
    __shared__ float bufB[32][68];
    float logw = -expf(tdcy[h]);
    int lrow = tid >> 3, lcol = (tid & 7) * 8;
    int td = (tid >> 4) * 4, te2 = (tid & 15) * 4;
    size_t base = ((size_t)(b*SEQ + c*CK)) * DM + h * 64;
    float sacc[4][4] = {};
    for (int s4 = 0; s4 < 4; s4++) {
        int j = s4 * 32 + lrow;
        float wk = expf(logw * (float)(127 - j));
        const float* ksrc = g_k + base + (size_t)j * DM + lcol;
        const float* vsrc = g_v + base + (size_t)j * DM + lcol;
        float4 k0 = *(const float4*)ksrc;
        float4 k1 = *(const float4*)(ksrc + 4);
        float4 w0 = *(const float4*)vsrc;
        float4 w1 = *(const float4*)(vsrc + 4);
        k0.x *= wk; k0.y *= wk; k0.z *= wk; k0.w *= wk;
        k1.x *= wk; k1.y *= wk; k1.z *= wk; k1.w *= wk;
        *(float4*)&bufA[lrow][lcol]     = k0;
        *(float4*)&bufA[lrow][lcol + 4] = k1;
        *(float4*)&bufB[lrow][lcol]     = w0;
        *(float4*)&bufB[lrow][lcol + 4] = w1;
        __syncthreads();
#pragma unroll 4
        for (int jj = 0; jj < 32; jj++) {
            float4 ka = *(const float4*)&bufA[jj][td];
            float4 vb = *(const float4*)&bufB[jj][te2];
            float ar[4] = {ka.x,ka.y,ka.z,ka.w};
            float br[4] = {vb.x,vb.y,vb.z,vb.w};
#pragma unroll
            for (int x = 0; x < 4; x++)
#pragma unroll
                for (int y = 0; y < 4; y++)
                    sacc[x][y] += ar[x] * br[y];
        }
        __syncthreads();
    }
    size_t obase = ((size_t)bh * NC + c) * 4096;
#pragma unroll
    for (int x = 0; x < 4; x++)
#pragma unroll
        for (int y = 0; y < 4; y++)
            g_kv[obase + (size_t)(td + x) * 64 + te2 + y] = sacc[x][y];
}

__global__ void combine_kernel(const float* __restrict__ tdcy,
                               float* __restrict__ state_out)
{
    int bh = blockIdx.x;
    int h = bh & 31;
    int tid = threadIdx.x;
    float wC = expf(-expf(tdcy[h]) * 128.f);
    float st[16];
#pragma unroll
    for (int q = 0; q < 16; q++) st[q] = 0.f;
    size_t base = (size_t)bh * NC * 4096;
    for (int c = 0; c < NC; c++) {
        size_t off = base + (size_t)c * 4096;
#pragma unroll
        for (int q = 0; q < 16; q++) {
            size_t idx = off + q * 256 + tid;
            g_state[idx] = st[q];
            st[q] = st[q] * wC + g_kv[idx];
        }
    }
#pragma unroll
    for (int q = 0; q < 16; q++)
        state_out[(size_t)bh * 4096 + q * 256 + tid] = st[q];
}

__global__ void bias_kernel(const float* __restrict__ tdcy)
{
    int c = blockIdx.x, bh = blockIdx.y;
    int h = bh & 31, b = bh >> 5;
    int tid = threadIdx.x;
    __shared__ float rs[64][132];
    __shared__ float ss[64][68];
    {
        int lrow = tid >> 1, lc = (tid & 1) * 32;
        size_t rbase = ((size_t)(b*SEQ + c*CK + lrow)) * DM + h * 64 + lc;
#pragma unroll
        for (int m = 0; m < 8; m++) {
            float4 rv = *(const float4*)(g_r + rbase + m * 4);
            int d = lc + m * 4;
            rs[d+0][lrow] = rv.x; rs[d+1][lrow] = rv.y;
            rs[d+2][lrow] = rv.z; rs[d+3][lrow] = rv.w;
        }
        size_t sbase = ((size_t)bh * NC + c) * 4096;
#pragma unroll
        for (int q = 0; q < 16; q++) {
            int idx = q * 256 + tid;
            ss[idx >> 6][idx & 63] = g_state[sbase + idx];
        }
    }
    __syncthreads();
    int ty = tid >> 3, tx = tid & 7;
    float acc[4][8] = {};
#pragma unroll 4
    for (int d = 0; d < 64; d++) {
        float4 a  = *(const float4*)&rs[d][ty * 4];
        float4 b0 = *(const float4*)&ss[d][tx * 8];
        float4 b1 = *(const float4*)&ss[d][tx * 8 + 4];
        float ar[4] = {a.x,a.y,a.z,a.w};
        float br[8] = {b0.x,b0.y,b0.z,b0.w,b1.x,b1.y,b1.z,b1.w};
#pragma unroll
        for (int x = 0; x < 4; x++)
#pragma unroll
            for (int e = 0; e < 8; e++)
                acc[x][e] += ar[x] * br[e];
    }
    float logw = -expf(tdcy[h]);
    size_t obase = ((size_t)(b*SEQ + c*CK)) * DM + h * 64;
#pragma unroll
    for (int x = 0; x < 4; x++) {
        int i = ty * 4 + x;
        float wi = expf(logw * (float)i);
        float* dst = g_att + obase + (size_t)i * DM + tx * 8;
        float4 o0 = *(float4*)dst;
        float4 o1 = *(float4*)(dst + 4);
        o0.x += wi * acc[x][0]; o0.y += wi * acc[x][1];
        o0.z += wi * acc[x][2]; o0.w += wi * acc[x][3];
        o1.x += wi * acc[x][4]; o1.y += wi * acc[x][5];
        o1.z += wi * acc[x][6]; o1.w += wi * acc[x][7];
        *(float4*)dst = o0;
        *(float4*)(dst + 4) = o1;
    }
}

// ---------------- per-head LN: g_att (fp32) -> g_atth (fp16) ----------------
__global__ void lnx_kernel(const float* __restrict__ sc,
                           const float* __restrict__ bi)
{
    int w = blockIdx.x * 8 + (threadIdx.x >> 5);
    int lid = threadIdx.x & 31;
    int h = w & 31;
    size_t row = (size_t)(w >> 5);
    const float* p = g_att + row * DM + h * 64;
    __half* po = g_atth + row * DM + h * 64;
    float x0 = p[lid], x1 = p[lid + 32];
    float s = x0 + x1, q = x0 * x0 + x1 * x1;
#pragma unroll
    for (int o = 16; o > 0; o >>= 1) {
        s += __shfl_xor_sync(0xffffffffu, s, o);
        q += __shfl_xor_sync(0xffffffffu, q, o);
    }
    float mu  = s * (1.f / 64.f);
    float inv = rsqrtf(q * (1.f / 64.f) - mu * mu + 1e-5f);
    po[lid]      = __float2half((x0 - mu) * inv * sc[h * 64 + lid]      + bi[h * 64 + lid]);
    po[lid + 32] = __float2half((x1 - mu) * inv * sc[h * 64 + lid + 32] + bi[h * 64 + lid + 32]);
}

// ---------------- launch ----------------
extern "C" void kernel_launch(void* const* d_in, const int* in_sizes, int n_in,
                              void* d_out, int out_size)
{
    const float* inputs = (const float*)d_in[0];
    const float* tmr    = (const float*)d_in[1];
    const float* tmk    = (const float*)d_in[2];
    const float* tmv    = (const float*)d_in[3];
    const float* Wk     = (const float*)d_in[4];
    const float* Wv     = (const float*)d_in[5];
    const float* Wr     = (const float*)d_in[6];
    const float* Wo     = (const float*)d_in[7];
    const float* tdcy   = (const float*)d_in[8];
    const float* tfirst = (const float*)d_in[9];
    const float* ln1s   = (const float*)d_in[10];
    const float* ln1b   = (const float*)d_in[11];
    const float* lnxs   = (const float*)d_in[12];
    const float* lnxb   = (const float*)d_in[13];

    float* out0      = (float*)d_out;
    float* out_xlast = out0 + (size_t)BZ * SEQ * DM;
    float* out_state = out_xlast + (size_t)BZ * DM;

    const int GSMEM = 4 * STG_BYTES;   // 49152 B
    cudaFuncSetAttribute(tgemm_kernel<0>, cudaFuncAttributeMaxDynamicSharedMemorySize, GSMEM);
    cudaFuncSetAttribute(tgemm_kernel<1>, cudaFuncAttributeMaxDynamicSharedMemorySize, GSMEM);
    cudaFuncSetAttribute(tgemm_kernel<2>, cudaFuncAttributeMaxDynamicSharedMemorySize, GSMEM);
    cudaFuncSetAttribute(tgemm_kernel<3>, cudaFuncAttributeMaxDynamicSharedMemorySize, GSMEM);
    cudaFuncSetAttribute(att_kernel,      cudaFuncAttributeMaxDynamicSharedMemorySize, ATT_SMEM);

    __half* wtr; __half* wtk; __half* wtv; __half* wto;
    cudaGetSymbolAddress((void**)&wtr, g_wtr);
    cudaGetSymbolAddress((void**)&wtk, g_wtk);
    cudaGetSymbolAddress((void**)&wtv, g_wtv);
    cudaGetSymbolAddress((void**)&wto, g_wto);

    transpose4_kernel<<<dim3(64, 64, 4), dim3(32, 8)>>>(Wr, wtr, Wk, wtk, Wv, wtv, Wo, wto);
    lnmix_kernel<<<MROWS, 256>>>(inputs, ln1s, ln1b, tmr, tmk, tmv, out_xlast);

    dim3 g(DM / 128, MROWS / 128);
    tgemm_kernel<0><<<g, 256, GSMEM>>>(wtr, nullptr, nullptr);
    tgemm_kernel<1><<<g, 256, GSMEM>>>(wtk, nullptr, nullptr);
    tgemm_kernel<2><<<g, 256, GSMEM>>>(wtv, nullptr, nullptr);
    att_kernel<<<BZ * NC * NH, 256, ATT_SMEM>>>(tdcy, tfirst);
    kv_kernel<<<dim3(NC, BZ * NH), 256>>>(tdcy);
    combine_kernel<<<BZ * NH, 256>>>(tdcy, out_state);
    bias_kernel<<<dim3(NC, BZ * NH), 256>>>(tdcy);
    lnx_kernel<<<(MROWS * NH) / 8, 256>>>(lnxs, lnxb);
    tgemm_kernel<3><<<g, 256, GSMEM>>>(wto, inputs, out0);
}

// round 14
// speedup vs baseline: 1.1887x; 1.1887x over previous
#include <cuda_runtime.h>
#include <cuda_fp16.h>
#include <cstdint>

#define SEQ   2048
#define DM    2048
#define NH    32
#define DH    64
#define CK    128
#define NC    16
#define BZ    4
#define MROWS (BZ*SEQ)   // 8192
#define BK    16
#define NKT   (DM/BK)    // 128

// ---------------- scratch (device globals; no allocation) ----------------
__device__ __align__(256) __half g_rxh [BZ*SEQ*DM];
__device__ __align__(256) __half g_kxh [BZ*SEQ*DM];
__device__ __align__(256) __half g_vxh [BZ*SEQ*DM];
__device__ __align__(256) __half g_atth[BZ*SEQ*DM];
__device__ float g_r  [BZ*SEQ*DM];
__device__ float g_k  [BZ*SEQ*DM];
__device__ float g_v  [BZ*SEQ*DM];
__device__ float g_att[BZ*SEQ*DM];
__device__ float g_kv   [BZ*NH*NC*DH*DH];
__device__ float g_state[BZ*NH*NC*DH*DH];
__device__ __align__(256) __half g_wtr[DM*DM];
__device__ __align__(256) __half g_wtk[DM*DM];
__device__ __align__(256) __half g_wtv[DM*DM];
__device__ __align__(256) __half g_wto[DM*DM];

// ---------------- small PTX helpers ----------------
__device__ __forceinline__ uint32_t smem_u32(const void* p)
{
    uint32_t a;
    asm("{ .reg .u64 t; cvta.to.shared.u64 t, %1; cvt.u32.u64 %0, t; }" : "=r"(a) : "l"(p));
    return a;
}
template<int N> __device__ __forceinline__ void cp_wait()
{
    asm volatile("cp.async.wait_group %0;" :: "n"(N) : "memory");
}
__device__ __forceinline__ void cp16(uint32_t dst, const void* src)
{
    asm volatile("cp.async.cg.shared.global [%0], [%1], 16;" :: "r"(dst), "l"(src));
}
__device__ __forceinline__ void cp_commit()
{
    asm volatile("cp.async.commit_group;" ::: "memory");
}
__device__ __forceinline__ void mma_f16(float* c, const unsigned* a, const unsigned* b)
{
    asm volatile(
        "mma.sync.aligned.m16n8k16.row.col.f32.f16.f16.f32 "
        "{%0,%1,%2,%3}, {%4,%5,%6,%7}, {%8,%9}, {%0,%1,%2,%3};"
        : "+f"(c[0]), "+f"(c[1]), "+f"(c[2]), "+f"(c[3])
        : "r"(a[0]), "r"(a[1]), "r"(a[2]), "r"(a[3]),
          "r"(b[0]), "r"(b[1]));
}
__device__ __forceinline__ void ldsm4(unsigned* r, uint32_t addr)
{
    asm volatile("ldmatrix.sync.aligned.m8n8.x4.shared.b16 {%0,%1,%2,%3}, [%4];"
        : "=r"(r[0]), "=r"(r[1]), "=r"(r[2]), "=r"(r[3]) : "r"(addr));
}
__device__ __forceinline__ void ldsm4t(unsigned* r, uint32_t addr)
{
    asm volatile("ldmatrix.sync.aligned.m8n8.x4.trans.shared.b16 {%0,%1,%2,%3}, [%4];"
        : "=r"(r[0]), "=r"(r[1]), "=r"(r[2]), "=r"(r[3]) : "r"(addr));
}

// ---------------- fused LN + token-shift mixing (fp16 outputs) ------------
__global__ void lnmix_kernel(const float* __restrict__ x,
                             const float* __restrict__ sc,
                             const float* __restrict__ bi,
                             const float* __restrict__ tmr,
                             const float* __restrict__ tmk,
                             const float* __restrict__ tmv,
                             float* __restrict__ xlast)
{
    int row = blockIdx.x;
    int t   = row & (SEQ - 1);
    const float* xr = x + (size_t)row * DM;
    float cur[8], prv[8];
    float s0 = 0.f, q0 = 0.f, s1 = 0.f, q1 = 0.f;
#pragma unroll
    for (int i = 0; i < 8; i++) {
        int c = threadIdx.x + i * 256;
        float v = xr[c];
        cur[i] = v; s0 += v; q0 += v * v;
        float u = t ? xr[c - DM] : 0.f;
        prv[i] = u; s1 += u; q1 += u * u;
    }
#pragma unroll
    for (int o = 16; o > 0; o >>= 1) {
        s0 += __shfl_xor_sync(0xffffffffu, s0, o);
        q0 += __shfl_xor_sync(0xffffffffu, q0, o);
        s1 += __shfl_xor_sync(0xffffffffu, s1, o);
        q1 += __shfl_xor_sync(0xffffffffu, q1, o);
    }
    __shared__ float rs0[8], rq0[8], rs1[8], rq1[8];
    int w = threadIdx.x >> 5;
    if ((threadIdx.x & 31) == 0) { rs0[w] = s0; rq0[w] = q0; rs1[w] = s1; rq1[w] = q1; }
    __syncthreads();
    s0 = 0.f; q0 = 0.f; s1 = 0.f; q1 = 0.f;
#pragma unroll
    for (int i = 0; i < 8; i++) { s0 += rs0[i]; q0 += rq0[i]; s1 += rs1[i]; q1 += rq1[i]; }
    float mu0  = s0 * (1.f / DM);
    float inv0 = rsqrtf(q0 * (1.f / DM) - mu0 * mu0 + 1e-5f);
    float mu1  = s1 * (1.f / DM);
    float inv1 = rsqrtf(q1 * (1.f / DM) - mu1 * mu1 + 1e-5f);
    bool last = (t == SEQ - 1);
#pragma unroll
    for (int i = 0; i < 8; i++) {
        int c = threadIdx.x + i * 256;
        float yc = (cur[i] - mu0) * inv0 * sc[c] + bi[c];
        float yp = t ? (prv[i] - mu1) * inv1 * sc[c] + bi[c] : 0.f;
        size_t off = (size_t)row * DM + c;
        float mr = tmr[c], mk = tmk[c], mv = tmv[c];
        g_rxh[off] = __float2half(yc * mr + (1.f - mr) * yp);
        g_kxh[off] = __float2half(yc * mk + (1.f - mk) * yp);
        g_vxh[off] = __float2half(yc * mv + (1.f - mv) * yp);
        if (last) xlast[(row >> 11) * DM + c] = yc;
    }
}

// ---------------- 4 weight transposes in one launch (fp16 outputs) --------
__global__ void transpose4_kernel(const float* __restrict__ s0, __half* __restrict__ d0,
                                  const float* __restrict__ s1, __half* __restrict__ d1,
                                  const float* __restrict__ s2, __half* __restrict__ d2,
                                  const float* __restrict__ s3, __half* __restrict__ d3)
{
    const float* src; __half* dst;
    switch (blockIdx.z) {
        case 0:  src = s0; dst = d0; break;
        case 1:  src = s1; dst = d1; break;
        case 2:  src = s2; dst = d2; break;
        default: src = s3; dst = d3; break;
    }
    __shared__ float t[32][33];
    int bx = blockIdx.x * 32, by = blockIdx.y * 32;
#pragma unroll
    for (int i = 0; i < 4; i++)
        t[threadIdx.y + i * 8][threadIdx.x] =
            src[(size_t)(by + threadIdx.y + i * 8) * DM + bx + threadIdx.x];
    __syncthreads();
#pragma unroll
    for (int i = 0; i < 4; i++)
        dst[(size_t)(bx + threadIdx.y + i * 8) * DM + by + threadIdx.x] =
            __float2half(t[threadIdx.x][threadIdx.y + i * 8]);
}

// ---------------- fp16 mma.sync GEMM (R11 champion layout, verbatim) ------
#define HSTRIDE 24                        // halves per smem row (16 data + 8 pad)
#define STG_BYTES (2 * 128 * HSTRIDE * 2) // A tile + B tile per stage = 12288 B

template<int MODE>
__global__ void __launch_bounds__(256, 2) tgemm_kernel(const __half* __restrict__ Bt,
                                                       const float* __restrict__ Add,
                                                       float* __restrict__ Out)
{
    const __half* A;
    float* C;
    if constexpr (MODE == 0) { A = g_rxh; C = g_r; }
    else if constexpr (MODE == 1) { A = g_kxh; C = g_k; }
    else if constexpr (MODE == 2) { A = g_vxh; C = g_v; }
    else { A = g_atth; C = Out; }

    extern __shared__ char smem[];
    uint32_t sb = smem_u32(smem);
    int tid = threadIdx.x, lane = tid & 31, warp = tid >> 5;
    int r0 = lane >> 2, c0 = lane & 3;
    int wm = (warp >> 2) * 64, wn = (warp & 3) * 32;
    int bm = blockIdx.y * 128, bn = blockIdx.x * 128;

    const __half* Ag = A  + (size_t)bm * DM;
    const __half* Bg = Bt + (size_t)bn * DM;

    int lane7 = lane & 7;
    uint32_t a_off = (uint32_t)(((wm + ((lane >> 3) & 1) * 8 + lane7) * HSTRIDE
                                + ((lane >> 4) & 1) * 8) * 2);
    uint32_t b_off = (uint32_t)(((wn + ((lane >> 4) & 1) * 8 + lane7) * HSTRIDE
                                + ((lane >> 3) & 1) * 8) * 2);

    // copy: two threads per row, 16B each (R11 champion mapping)
    int cm = tid >> 1, cq = (tid & 1) * 8;
    auto copy_stage = [&](int buf, int kt) {
        uint32_t sA = sb + buf * STG_BYTES;
        uint32_t sB = sA + 128 * HSTRIDE * 2;
        uint32_t off = cm * (HSTRIDE * 2) + cq * 2;
        cp16(sA + off, Ag + kt * BK + (size_t)cm * DM + cq);
        cp16(sB + off, Bg + kt * BK + (size_t)cm * DM + cq);
        cp_commit();
    };

    float acc[4][4][4];
#pragma unroll
    for (int i = 0; i < 4; i++)
#pragma unroll
        for (int j = 0; j < 4; j++)
#pragma unroll
            for (int e = 0; e < 4; e++) acc[i][j][e] = 0.f;

    copy_stage(0, 0);
    copy_stage(1, 1);
    copy_stage(2, 2);
    cp_wait<2>();
    __syncthreads();

    for (int kt = 0; kt < NKT; kt++) {
        int buf = kt & 3;
        uint32_t sA = sb + buf * STG_BYTES;
        uint32_t sB = sA + 128 * HSTRIDE * 2;
        unsigned af[4][4], bf[8];
#pragma unroll
        for (int i = 0; i < 4; i++)
            ldsm4(af[i], sA + a_off + i * (16 * HSTRIDE * 2));
        ldsm4(&bf[0], sB + b_off);
        ldsm4(&bf[4], sB + b_off + 16 * HSTRIDE * 2);
#pragma unroll
        for (int i = 0; i < 4; i++)
#pragma unroll
            for (int j = 0; j < 4; j++)
                mma_f16(acc[i][j], af[i], &bf[j * 2]);
        // one commit-group per iteration (empty in tail) keeps wait<2>'s
        // "next tile resident" invariant
        if (kt + 3 < NKT) copy_stage((kt + 3) & 3, kt + 3);
        else              cp_commit();
        cp_wait<2>();
        __syncthreads();
    }

#pragma unroll
    for (int i = 0; i < 4; i++) {
        int row = bm + wm + i * 16 + r0;
#pragma unroll
        for (int j = 0; j < 4; j++) {
            int col = bn + wn + j * 8 + c0 * 2;
            size_t o0 = (size_t)row * DM + col;
            size_t o1 = (size_t)(row + 8) * DM + col;
            float2 v0 = make_float2(acc[i][j][0], acc[i][j][1]);
            float2 v1 = make_float2(acc[i][j][2], acc[i][j][3]);
            if constexpr (MODE == 3) {
                float2 a0 = *(const float2*)(Add + o0);
                float2 a1 = *(const float2*)(Add + o1);
                v0.x += a0.x; v0.y += a0.y;
                v1.x += a1.x; v1.y += a1.y;
            }
            *(float2*)(C + o0) = v0;
            *(float2*)(C + o1) = v1;
        }
    }
}

// ---------------- fused attention: sep = ((r@k^T)*mask) @ v ---------------
#define RSTR 72    // halves per row, r/k/v tiles (64 data + 8 pad)
#define SSTR 136   // halves per row, S tile (128 data + 8 pad)
#define ATT_SMEM (3 * 128 * RSTR * 2 + 128 * SSTR * 2)   // 90112 B

__global__ void __launch_bounds__(256, 2) att_kernel(const float* __restrict__ tdcy,
                                                     const float* __restrict__ tfirst)
{
    int bch = blockIdx.x;
    int h = bch & 31;
    int chunk = (bch >> 5) & 15;
    int b = bch >> 9;
    extern __shared__ char smem[];
    __half* rs = (__half*)smem;
    __half* ks = rs + 128 * RSTR;
    __half* vs = ks + 128 * RSTR;
    __half* ss = vs + 128 * RSTR;
    int tid = threadIdx.x, lane = tid & 31, warp = tid >> 5;
    int lane7 = lane & 7;
    int r0 = lane >> 2, c0 = lane & 3;

    size_t gbase = ((size_t)(b * SEQ + chunk * CK)) * DM + h * 64;
#pragma unroll
    for (int q = 0; q < 8; q++) {
        int idx = q * 256 + tid;
        int row = idx >> 4, cc = (idx & 15) * 4;
        size_t off = gbase + (size_t)row * DM + cc;
        float4 rv = *(const float4*)(g_r + off);
        float4 kv = *(const float4*)(g_k + off);
        float4 vv = *(const float4*)(g_v + off);
        __half2* rp = (__half2*)&rs[row * RSTR + cc];
        rp[0] = __floats2half2_rn(rv.x, rv.y); rp[1] = __floats2half2_rn(rv.z, rv.w);
        __half2* kp = (__half2*)&ks[row * RSTR + cc];
        kp[0] = __floats2half2_rn(kv.x, kv.y); kp[1] = __floats2half2_rn(kv.z, kv.w);
        __half2* vp = (__half2*)&vs[row * RSTR + cc];
        vp[0] = __floats2half2_rn(vv.x, vv.y); vp[1] = __floats2half2_rn(vv.z, vv.w);
    }
    __syncthreads();

    int wm = (warp >> 2) * 64, wn = (warp & 3) * 32;
    uint32_t rs_b = smem_u32(rs), ks_b = smem_u32(ks);
    uint32_t vs_b = smem_u32(vs), ss_b = smem_u32(ss);
    uint32_t a_off = rs_b + (uint32_t)(((wm + ((lane >> 3) & 1) * 8 + lane7) * RSTR
                                      + ((lane >> 4) & 1) * 8) * 2);
    uint32_t b_off = ks_b + (uint32_t)(((wn + ((lane >> 4) & 1) * 8 + lane7) * RSTR
                                      + ((lane >> 3) & 1) * 8) * 2);
    float acc[4][4][4];
#pragma unroll
    for (int i = 0; i < 4; i++)
#pragma unroll
        for (int j = 0; j < 4; j++)
#pragma unroll
            for (int e = 0; e < 4; e++) acc[i][j][e] = 0.f;
#pragma unroll
    for (int kb = 0; kb < 4; kb++) {
        unsigned af[4][4], bf[8];
#pragma unroll
        for (int i = 0; i < 4; i++)
            ldsm4(af[i], a_off + i * (16 * RSTR * 2) + kb * 32);
        ldsm4(&bf[0], b_off + kb * 32);
        ldsm4(&bf[4], b_off + 16 * RSTR * 2 + kb * 32);
#pragma unroll
        for (int i = 0; i < 4; i++)
#pragma unroll
            for (int j = 0; j < 4; j++)
                mma_f16(acc[i][j], af[i], &bf[j * 2]);
    }

    float logw = -expf(tdcy[h]);
    float u    =  expf(tfirst[h]);
#pragma unroll
    for (int i = 0; i < 4; i++) {
#pragma unroll
        for (int j = 0; j < 4; j++) {
            int ri = wm + i * 16 + r0;
            int cj = wn + j * 8 + c0 * 2;
#pragma unroll
            for (int e = 0; e < 4; e++) {
                int rr = ri + (e >> 1) * 8;
                int cc = cj + (e & 1);
                float m;
                if (rr > cc)       m = expf(logw * (float)(rr - cc - 1));
                else if (rr == cc) m = u;
                else               m = 0.f;
                ss[rr * SSTR + cc] = __float2half(acc[i][j][e] * m);
            }
        }
    }
    __syncthreads();

    int wm2 = (warp >> 2) * 64, wn2 = (warp & 3) * 16;
    uint32_t a2 = ss_b + (uint32_t)(((wm2 + ((lane >> 3) & 1) * 8 + lane7) * SSTR
                                   + ((lane >> 4) & 1) * 8) * 2);
    uint32_t bt = vs_b + (uint32_t)(((((lane >> 3) & 1) * 8 + lane7) * RSTR
                                   + wn2 + ((lane >> 4) & 1) * 8) * 2);
    float acc2[4][2][4];
#pragma unroll
    for (int i = 0; i < 4; i++)
#pragma unroll
        for (int j = 0; j < 2; j++)
#pragma unroll
            for (int e = 0; e < 4; e++) acc2[i][j][e] = 0.f;
#pragma unroll
    for (int kb = 0; kb < 8; kb++) {
        unsigned af[4][4], bf[4];
#pragma unroll
        for (int i = 0; i < 4; i++)
            ldsm4(af[i], a2 + i * (16 * SSTR * 2) + kb * 32);
        ldsm4t(bf, bt + kb * (16 * RSTR * 2));
#pragma unroll
        for (int i = 0; i < 4; i++)
#pragma unroll
            for (int j = 0; j < 2; j++)
                mma_f16(acc2[i][j], af[i], &bf[j * 2]);
    }
#pragma unroll
    for (int i = 0; i < 4; i++) {
        int row = wm2 + i * 16 + r0;
        size_t o = ((size_t)(b * SEQ + chunk * CK + row)) * DM + h * 64;
#pragma unroll
        for (int j = 0; j < 2; j++) {
            int col = wn2 + j * 8 + c0 * 2;
            *(float2*)(g_att + o + col) = make_float2(acc2[i][j][0], acc2[i][j][1]);
            *(float2*)(g_att + o + (size_t)8 * DM + col) = make_float2(acc2[i][j][2], acc2[i][j][3]);
        }
    }
}

// ---------------- scan decomposition ----------------
__global__ void kv_kernel(const float* __restrict__ tdcy)
{
    int c = blockIdx.x, bh = blockIdx.y;
    int h = bh & 31, b = bh >> 5;
    int tid = threadIdx.x;
    __shared__ float bufA[32][68];
    __shared__ float bufB[32][68];
    float logw = -expf(tdcy[h]);
    int lrow = tid >> 3, lcol = (tid & 7) * 8;
    int td = (tid >> 4) * 4, te2 = (tid & 15) * 4;
    size_t base = ((size_t)(b*SEQ + c*CK)) * DM + h * 64;
    float sacc[4][4] = {};
    for (int s4 = 0; s4 < 4; s4++) {
        int j = s4 * 32 + lrow;
        float wk = expf(logw * (float)(127 - j));
        const float* ksrc = g_k + base + (size_t)j * DM + lcol;
        const float* vsrc = g_v + base + (size_t)j * DM + lcol;
        float4 k0 = *(const float4*)ksrc;
        float4 k1 = *(const float4*)(ksrc + 4);
        float4 w0 = *(const float4*)vsrc;
        float4 w1 = *(const float4*)(vsrc + 4);
        k0.x *= wk; k0.y *= wk; k0.z *= wk; k0.w *= wk;
        k1.x *= wk; k1.y *= wk; k1.z *= wk; k1.w *= wk;
        *(float4*)&bufA[lrow][lcol]     = k0;
        *(float4*)&bufA[lrow][lcol + 4] = k1;
        *(float4*)&bufB[lrow][lcol]     = w0;
        *(float4*)&bufB[lrow][lcol + 4] = w1;
        __syncthreads();
#pragma unroll 4
        for (int jj = 0; jj < 32; jj++) {
            float4 ka = *(const float4*)&bufA[jj][td];
            float4 vb = *(const float4*)&bufB[jj][te2];
            float ar[4] = {ka.x,ka.y,ka.z,ka.w};
            float br[4] = {vb.x,vb.y,vb.z,vb.w};
#pragma unroll
            for (int x = 0; x < 4; x++)
#pragma unroll
                for (int y = 0; y < 4; y++)
                    sacc[x][y] += ar[x] * br[y];
        }
        __syncthreads();
    }
    size_t obase = ((size_t)bh * NC + c) * 4096;
#pragma unroll
    for (int x = 0; x < 4; x++)
#pragma unroll
        for (int y = 0; y < 4; y++)
            g_kv[obase + (size_t)(td + x) * 64 + te2 + y] = sacc[x][y];
}

__global__ void combine_kernel(const float* __restrict__ tdcy,
                               float* __restrict__ state_out)
{
    int bh = blockIdx.x;
    int h = bh & 31;
    int tid = threadIdx.x;
    float wC = expf(-expf(tdcy[h]) * 128.f);
    float st[16];
#pragma unroll
    for (int q = 0; q < 16; q++) st[q] = 0.f;
    size_t base = (size_t)bh * NC * 4096;
    for (int c = 0; c < NC; c++) {
        size_t off = base + (size_t)c * 4096;
#pragma unroll
        for (int q = 0; q < 16; q++) {
            size_t idx = off + q * 256 + tid;
            g_state[idx] = st[q];
            st[q] = st[q] * wC + g_kv[idx];
        }
    }
#pragma unroll
    for (int q = 0; q < 16; q++)
        state_out[(size_t)bh * 4096 + q * 256 + tid] = st[q];
}

// ---------------- bias + per-head LN fused: writes g_atth directly --------
__global__ void bias_lnx_kernel(const float* __restrict__ tdcy,
                                const float* __restrict__ lsc,
                                const float* __restrict__ lbi)
{
    int c = blockIdx.x, bh = blockIdx.y;
    int h = bh & 31, b = bh >> 5;
    int tid = threadIdx.x;
    __shared__ float rs[64][132];
    __shared__ float ss[64][68];
    {
        int lrow = tid >> 1, lc = (tid & 1) * 32;
        size_t rbase = ((size_t)(b*SEQ + c*CK + lrow)) * DM + h * 64 + lc;
#pragma unroll
        for (int m = 0; m < 8; m++) {
            float4 rv = *(const float4*)(g_r + rbase + m * 4);
            int d = lc + m * 4;
            rs[d+0][lrow] = rv.x; rs[d+1][lrow] = rv.y;
            rs[d+2][lrow] = rv.z; rs[d+3][lrow] = rv.w;
        }
        size_t sbase = ((size_t)bh * NC + c) * 4096;
#pragma unroll
        for (int q = 0; q < 16; q++) {
            int idx = q * 256 + tid;
            ss[idx >> 6][idx & 63] = g_state[sbase + idx];
        }
    }
    __syncthreads();
    int ty = tid >> 3, tx = tid & 7;
    float acc[4][8] = {};
#pragma unroll 4
    for (int d = 0; d < 64; d++) {
        float4 a  = *(const float4*)&rs[d][ty * 4];
        float4 b0 = *(const float4*)&ss[d][tx * 8];
        float4 b1 = *(const float4*)&ss[d][tx * 8 + 4];
        float ar[4] = {a.x,a.y,a.z,a.w};
        float br[8] = {b0.x,b0.y,b0.z,b0.w,b1.x,b1.y,b1.z,b1.w};
#pragma unroll
        for (int x = 0; x < 4; x++)
#pragma unroll
            for (int e = 0; e < 8; e++)
                acc[x][e] += ar[x] * br[e];
    }
    float logw = -expf(tdcy[h]);
    size_t obase = ((size_t)(b*SEQ + c*CK)) * DM + h * 64;
    // row ty*4+x's 64 values live in the 8 consecutive lanes tx=0..7 of this ty
#pragma unroll
    for (int x = 0; x < 4; x++) {
        int i = ty * 4 + x;
        float wi = expf(logw * (float)i);
        const float* src = g_att + obase + (size_t)i * DM + tx * 8;
        float v[8];
        float4 o0 = *(const float4*)src;
        float4 o1 = *(const float4*)(src + 4);
        v[0] = o0.x + wi * acc[x][0]; v[1] = o0.y + wi * acc[x][1];
        v[2] = o0.z + wi * acc[x][2]; v[3] = o0.w + wi * acc[x][3];
        v[4] = o1.x + wi * acc[x][4]; v[5] = o1.y + wi * acc[x][5];
        v[6] = o1.z + wi * acc[x][6]; v[7] = o1.w + wi * acc[x][7];
        float s = 0.f, q = 0.f;
#pragma unroll
        for (int e = 0; e < 8; e++) { s += v[e]; q += v[e] * v[e]; }
#pragma unroll
        for (int o = 4; o > 0; o >>= 1) {
            s += __shfl_xor_sync(0xffffffffu, s, o);
            q += __shfl_xor_sync(0xffffffffu, q, o);
        }
        float mu  = s * (1.f / 64.f);
        float inv = rsqrtf(q * (1.f / 64.f) - mu * mu + 1e-5f);
        __half2 hv[4];
#pragma unroll
        for (int e = 0; e < 4; e++) {
            int c0i = h * 64 + tx * 8 + e * 2;
            float y0 = (v[e*2]   - mu) * inv * lsc[c0i]     + lbi[c0i];
            float y1 = (v[e*2+1] - mu) * inv * lsc[c0i + 1] + lbi[c0i + 1];
            hv[e] = __floats2half2_rn(y0, y1);
        }
        *(uint4*)(g_atth + obase + (size_t)i * DM + tx * 8) =
            *(uint4*)hv;
    }
}

// ---------------- launch ----------------
extern "C" void kernel_launch(void* const* d_in, const int* in_sizes, int n_in,
                              void* d_out, int out_size)
{
    const float* inputs = (const float*)d_in[0];
    const float* tmr    = (const float*)d_in[1];
    const float* tmk    = (const float*)d_in[2];
    const float* tmv    = (const float*)d_in[3];
    const float* Wk     = (const float*)d_in[4];
    const float* Wv     = (const float*)d_in[5];
    const float* Wr     = (const float*)d_in[6];
    const float* Wo     = (const float*)d_in[7];
    const float* tdcy   = (const float*)d_in[8];
    const float* tfirst = (const float*)d_in[9];
    const float* ln1s   = (const float*)d_in[10];
    const float* ln1b   = (const float*)d_in[11];
    const float* lnxs   = (const float*)d_in[12];
    const float* lnxb   = (const float*)d_in[13];

    float* out0      = (float*)d_out;
    float* out_xlast = out0 + (size_t)BZ * SEQ * DM;
    float* out_state = out_xlast + (size_t)BZ * DM;

    const int GSMEM = 4 * STG_BYTES;   // 49152 B
    cudaFuncSetAttribute(tgemm_kernel<0>, cudaFuncAttributeMaxDynamicSharedMemorySize, GSMEM);
    cudaFuncSetAttribute(tgemm_kernel<1>, cudaFuncAttributeMaxDynamicSharedMemorySize, GSMEM);
    cudaFuncSetAttribute(tgemm_kernel<2>, cudaFuncAttributeMaxDynamicSharedMemorySize, GSMEM);
    cudaFuncSetAttribute(tgemm_kernel<3>, cudaFuncAttributeMaxDynamicSharedMemorySize, GSMEM);
    cudaFuncSetAttribute(att_kernel,      cudaFuncAttributeMaxDynamicSharedMemorySize, ATT_SMEM);

    __half* wtr; __half* wtk; __half* wtv; __half* wto;
    cudaGetSymbolAddress((void**)&wtr, g_wtr);
    cudaGetSymbolAddress((void**)&wtk, g_wtk);
    cudaGetSymbolAddress((void**)&wtv, g_wtv);
    cudaGetSymbolAddress((void**)&wto, g_wto);

    transpose4_kernel<<<dim3(64, 64, 4), dim3(32, 8)>>>(Wr, wtr, Wk, wtk, Wv, wtv, Wo, wto);
    lnmix_kernel<<<MROWS, 256>>>(inputs, ln1s, ln1b, tmr, tmk, tmv, out_xlast);

    dim3 g(DM / 128, MROWS / 128);
    tgemm_kernel<0><<<g, 256, GSMEM>>>(wtr, nullptr, nullptr);
    tgemm_kernel<1><<<g, 256, GSMEM>>>(wtk, nullptr, nullptr);
    tgemm_kernel<2><<<g, 256, GSMEM>>>(wtv, nullptr, nullptr);
    att_kernel<<<BZ * NC * NH, 256, ATT_SMEM>>>(tdcy, tfirst);
    kv_kernel<<<dim3(NC, BZ * NH), 256>>>(tdcy);
    combine_kernel<<<BZ * NH, 256>>>(tdcy, out_state);
    bias_lnx_kernel<<<dim3(NC, BZ * NH), 256>>>(tdcy, lnxs, lnxb);
    tgemm_kernel<3><<<g, 256, GSMEM>>>(wto, inputs, out0);
}

// round 15
// speedup vs baseline: 1.2393x; 1.0425x over previous
#include <cuda_runtime.h>
#include <cuda_fp16.h>
#include <cstdint>

#define SEQ   2048
#define DM    2048
#define NH    32
#define DH    64
#define CK    128
#define NC    16
#define BZ    4
#define MROWS (BZ*SEQ)   // 8192
#define BK    16
#define NKT   (DM/BK)    // 128
#define STAGES 5

// ---------------- scratch (device globals; no allocation) ----------------
__device__ __align__(256) __half g_rxh [BZ*SEQ*DM];
__device__ __align__(256) __half g_kxh [BZ*SEQ*DM];
__device__ __align__(256) __half g_vxh [BZ*SEQ*DM];
__device__ __align__(256) __half g_atth[BZ*SEQ*DM];
__device__ __align__(256) __half g_rh  [BZ*SEQ*DM];
__device__ __align__(256) __half g_kh  [BZ*SEQ*DM];
__device__ __align__(256) __half g_vh  [BZ*SEQ*DM];
__device__ float g_r  [BZ*SEQ*DM];
__device__ float g_k  [BZ*SEQ*DM];
__device__ float g_v  [BZ*SEQ*DM];
__device__ float g_att[BZ*SEQ*DM];
__device__ float g_kv   [BZ*NH*NC*DH*DH];
__device__ float g_state[BZ*NH*NC*DH*DH];
__device__ __align__(256) __half g_wtr[DM*DM];
__device__ __align__(256) __half g_wtk[DM*DM];
__device__ __align__(256) __half g_wtv[DM*DM];
__device__ __align__(256) __half g_wto[DM*DM];

// ---------------- small PTX helpers ----------------
__device__ __forceinline__ uint32_t smem_u32(const void* p)
{
    uint32_t a;
    asm("{ .reg .u64 t; cvta.to.shared.u64 t, %1; cvt.u32.u64 %0, t; }" : "=r"(a) : "l"(p));
    return a;
}
template<int N> __device__ __forceinline__ void cp_wait()
{
    asm volatile("cp.async.wait_group %0;" :: "n"(N) : "memory");
}
__device__ __forceinline__ void cp16(uint32_t dst, const void* src)
{
    asm volatile("cp.async.cg.shared.global [%0], [%1], 16;" :: "r"(dst), "l"(src));
}
__device__ __forceinline__ void cp_commit()
{
    asm volatile("cp.async.commit_group;" ::: "memory");
}
__device__ __forceinline__ void mma_f16(float* c, const unsigned* a, const unsigned* b)
{
    asm volatile(
        "mma.sync.aligned.m16n8k16.row.col.f32.f16.f16.f32 "
        "{%0,%1,%2,%3}, {%4,%5,%6,%7}, {%8,%9}, {%0,%1,%2,%3};"
        : "+f"(c[0]), "+f"(c[1]), "+f"(c[2]), "+f"(c[3])
        : "r"(a[0]), "r"(a[1]), "r"(a[2]), "r"(a[3]),
          "r"(b[0]), "r"(b[1]));
}
__device__ __forceinline__ void ldsm4(unsigned* r, uint32_t addr)
{
    asm volatile("ldmatrix.sync.aligned.m8n8.x4.shared.b16 {%0,%1,%2,%3}, [%4];"
        : "=r"(r[0]), "=r"(r[1]), "=r"(r[2]), "=r"(r[3]) : "r"(addr));
}
__device__ __forceinline__ void ldsm4t(unsigned* r, uint32_t addr)
{
    asm volatile("ldmatrix.sync.aligned.m8n8.x4.trans.shared.b16 {%0,%1,%2,%3}, [%4];"
        : "=r"(r[0]), "=r"(r[1]), "=r"(r[2]), "=r"(r[3]) : "r"(addr));
}

// ---------------- fused LN + token-shift mixing (fp16 outputs) ------------
__global__ void lnmix_kernel(const float* __restrict__ x,
                             const float* __restrict__ sc,
                             const float* __restrict__ bi,
                             const float* __restrict__ tmr,
                             const float* __restrict__ tmk,
                             const float* __restrict__ tmv,
                             float* __restrict__ xlast)
{
    int row = blockIdx.x;
    int t   = row & (SEQ - 1);
    const float* xr = x + (size_t)row * DM;
    float cur[8], prv[8];
    float s0 = 0.f, q0 = 0.f, s1 = 0.f, q1 = 0.f;
#pragma unroll
    for (int i = 0; i < 8; i++) {
        int c = threadIdx.x + i * 256;
        float v = xr[c];
        cur[i] = v; s0 += v; q0 += v * v;
        float u = t ? xr[c - DM] : 0.f;
        prv[i] = u; s1 += u; q1 += u * u;
    }
#pragma unroll
    for (int o = 16; o > 0; o >>= 1) {
        s0 += __shfl_xor_sync(0xffffffffu, s0, o);
        q0 += __shfl_xor_sync(0xffffffffu, q0, o);
        s1 += __shfl_xor_sync(0xffffffffu, s1, o);
        q1 += __shfl_xor_sync(0xffffffffu, q1, o);
    }
    __shared__ float rs0[8], rq0[8], rs1[8], rq1[8];
    int w = threadIdx.x >> 5;
    if ((threadIdx.x & 31) == 0) { rs0[w] = s0; rq0[w] = q0; rs1[w] = s1; rq1[w] = q1; }
    __syncthreads();
    s0 = 0.f; q0 = 0.f; s1 = 0.f; q1 = 0.f;
#pragma unroll
    for (int i = 0; i < 8; i++) { s0 += rs0[i]; q0 += rq0[i]; s1 += rs1[i]; q1 += rq1[i]; }
    float mu0  = s0 * (1.f / DM);
    float inv0 = rsqrtf(q0 * (1.f / DM) - mu0 * mu0 + 1e-5f);
    float mu1  = s1 * (1.f / DM);
    float inv1 = rsqrtf(q1 * (1.f / DM) - mu1 * mu1 + 1e-5f);
    bool last = (t == SEQ - 1);
#pragma unroll
    for (int i = 0; i < 8; i++) {
        int c = threadIdx.x + i * 256;
        float yc = (cur[i] - mu0) * inv0 * sc[c] + bi[c];
        float yp = t ? (prv[i] - mu1) * inv1 * sc[c] + bi[c] : 0.f;
        size_t off = (size_t)row * DM + c;
        float mr = tmr[c], mk = tmk[c], mv = tmv[c];
        g_rxh[off] = __float2half(yc * mr + (1.f - mr) * yp);
        g_kxh[off] = __float2half(yc * mk + (1.f - mk) * yp);
        g_vxh[off] = __float2half(yc * mv + (1.f - mv) * yp);
        if (last) xlast[(row >> 11) * DM + c] = yc;
    }
}

// ---------------- 4 weight transposes in one launch (fp16 outputs) --------
__global__ void transpose4_kernel(const float* __restrict__ s0, __half* __restrict__ d0,
                                  const float* __restrict__ s1, __half* __restrict__ d1,
                                  const float* __restrict__ s2, __half* __restrict__ d2,
                                  const float* __restrict__ s3, __half* __restrict__ d3)
{
    const float* src; __half* dst;
    switch (blockIdx.z) {
        case 0:  src = s0; dst = d0; break;
        case 1:  src = s1; dst = d1; break;
        case 2:  src = s2; dst = d2; break;
        default: src = s3; dst = d3; break;
    }
    __shared__ float t[32][33];
    int bx = blockIdx.x * 32, by = blockIdx.y * 32;
#pragma unroll
    for (int i = 0; i < 4; i++)
        t[threadIdx.y + i * 8][threadIdx.x] =
            src[(size_t)(by + threadIdx.y + i * 8) * DM + bx + threadIdx.x];
    __syncthreads();
#pragma unroll
    for (int i = 0; i < 4; i++)
        dst[(size_t)(bx + threadIdx.y + i * 8) * DM + by + threadIdx.x] =
            __float2half(t[threadIdx.x][threadIdx.y + i * 8]);
}

// ---------------- fp16 mma.sync GEMM (R11 layout; 5-stage, sync every 2) --
#define HSTRIDE 24                        // halves per smem row (16 data + 8 pad)
#define STG_BYTES (2 * 128 * HSTRIDE * 2) // A tile + B tile per stage = 12288 B

template<int MODE>
__global__ void __launch_bounds__(256, 2) tgemm_kernel(const __half* __restrict__ Bt,
                                                       const float* __restrict__ Add,
                                                       float* __restrict__ Out)
{
    const __half* A;
    float* C;
    if constexpr (MODE == 0) { A = g_rxh; C = g_r; }
    else if constexpr (MODE == 1) { A = g_kxh; C = g_k; }
    else if constexpr (MODE == 2) { A = g_vxh; C = g_v; }
    else { A = g_atth; C = Out; }

    extern __shared__ char smem[];
    uint32_t sb = smem_u32(smem);
    int tid = threadIdx.x, lane = tid & 31, warp = tid >> 5;
    int r0 = lane >> 2, c0 = lane & 3;
    int wm = (warp >> 2) * 64, wn = (warp & 3) * 32;
    int bm = blockIdx.y * 128, bn = blockIdx.x * 128;

    const __half* Ag = A  + (size_t)bm * DM;
    const __half* Bg = Bt + (size_t)bn * DM;

    int lane7 = lane & 7;
    uint32_t a_off = (uint32_t)(((wm + ((lane >> 3) & 1) * 8 + lane7) * HSTRIDE
                                + ((lane >> 4) & 1) * 8) * 2);
    uint32_t b_off = (uint32_t)(((wn + ((lane >> 4) & 1) * 8 + lane7) * HSTRIDE
                                + ((lane >> 3) & 1) * 8) * 2);

    // copy: two threads per row, 16B each (R11 champion mapping)
    int cm = tid >> 1, cq = (tid & 1) * 8;
    auto copy_stage = [&](int buf, int kt) {
        uint32_t sA = sb + buf * STG_BYTES;
        uint32_t sB = sA + 128 * HSTRIDE * 2;
        uint32_t off = cm * (HSTRIDE * 2) + cq * 2;
        cp16(sA + off, Ag + kt * BK + (size_t)cm * DM + cq);
        cp16(sB + off, Bg + kt * BK + (size_t)cm * DM + cq);
        cp_commit();
    };

    float acc[4][4][4];
#pragma unroll
    for (int i = 0; i < 4; i++)
#pragma unroll
        for (int j = 0; j < 4; j++)
#pragma unroll
            for (int e = 0; e < 4; e++) acc[i][j][e] = 0.f;

    copy_stage(0, 0);
    copy_stage(1, 1);
    copy_stage(2, 2);
    cp_wait<1>();       // buffers 0,1 complete
    __syncthreads();

    // prefetch distance 3, 5 buffers: copy at kt overwrites buffer of kt-2;
    // sync at even kt guarantees all reads <= kt-1 done, and (with wait<1>)
    // buffers kt, kt+1 resident+visible for this iteration pair.
    int buf = 0, cbuf = 3;
    for (int kt = 0; kt < NKT; kt++) {
        if (kt && !(kt & 1)) {
            cp_wait<1>();
            __syncthreads();
        }
        uint32_t sA = sb + buf * STG_BYTES;
        uint32_t sB = sA + 128 * HSTRIDE * 2;
        unsigned af[4][4], bf[8];
#pragma unroll
        for (int i = 0; i < 4; i++)
            ldsm4(af[i], sA + a_off + i * (16 * HSTRIDE * 2));
        ldsm4(&bf[0], sB + b_off);
        ldsm4(&bf[4], sB + b_off + 16 * HSTRIDE * 2);
#pragma unroll
        for (int i = 0; i < 4; i++)
#pragma unroll
            for (int j = 0; j < 4; j++)
                mma_f16(acc[i][j], af[i], &bf[j * 2]);
        if (kt + 3 < NKT) copy_stage(cbuf, kt + 3);
        else              cp_commit();     // keep one group per iteration
        buf  = (buf  == STAGES - 1) ? 0 : buf + 1;
        cbuf = (cbuf == STAGES - 1) ? 0 : cbuf + 1;
    }

#pragma unroll
    for (int i = 0; i < 4; i++) {
        int row = bm + wm + i * 16 + r0;
#pragma unroll
        for (int j = 0; j < 4; j++) {
            int col = bn + wn + j * 8 + c0 * 2;
            size_t o0 = (size_t)row * DM + col;
            size_t o1 = (size_t)(row + 8) * DM + col;
            float2 v0 = make_float2(acc[i][j][0], acc[i][j][1]);
            float2 v1 = make_float2(acc[i][j][2], acc[i][j][3]);
            if constexpr (MODE == 3) {
                float2 a0 = *(const float2*)(Add + o0);
                float2 a1 = *(const float2*)(Add + o1);
                v0.x += a0.x; v0.y += a0.y;
                v1.x += a1.x; v1.y += a1.y;
            }
            *(float2*)(C + o0) = v0;
            *(float2*)(C + o1) = v1;
            if constexpr (MODE != 3) {
                __half* Ch = (MODE == 0) ? g_rh : (MODE == 1) ? g_kh : g_vh;
                *(__half2*)(Ch + o0) = __floats2half2_rn(v0.x, v0.y);
                *(__half2*)(Ch + o1) = __floats2half2_rn(v1.x, v1.y);
            }
        }
    }
}

// ---------------- fused attention: sep = ((r@k^T)*mask) @ v ---------------
#define RSTR 72    // halves per row, r/k/v tiles (64 data + 8 pad)
#define SSTR 136   // halves per row, S tile (128 data + 8 pad)
#define ATT_SMEM (3 * 128 * RSTR * 2 + 128 * SSTR * 2)   // 90112 B

__global__ void __launch_bounds__(256, 2) att_kernel(const float* __restrict__ tdcy,
                                                     const float* __restrict__ tfirst)
{
    int bch = blockIdx.x;
    int h = bch & 31;
    int chunk = (bch >> 5) & 15;
    int b = bch >> 9;
    extern __shared__ char smem[];
    __half* rs = (__half*)smem;
    __half* ks = rs + 128 * RSTR;
    __half* vs = ks + 128 * RSTR;
    __half* ss = vs + 128 * RSTR;
    int tid = threadIdx.x, lane = tid & 31, warp = tid >> 5;
    int lane7 = lane & 7;
    int r0 = lane >> 2, c0 = lane & 3;

    // stage r,k,v tiles directly from fp16 copies (bit-identical to the old
    // fp32-load + __floats2half2_rn path, now half the DRAM traffic)
    size_t gbase = ((size_t)(b * SEQ + chunk * CK)) * DM + h * 64;
#pragma unroll
    for (int q = 0; q < 4; q++) {
        int idx = q * 256 + tid;
        int row = idx >> 3, c8 = (idx & 7) * 8;
        size_t off = gbase + (size_t)row * DM + c8;
        *(uint4*)&rs[row * RSTR + c8] = *(const uint4*)(g_rh + off);
        *(uint4*)&ks[row * RSTR + c8] = *(const uint4*)(g_kh + off);
        *(uint4*)&vs[row * RSTR + c8] = *(const uint4*)(g_vh + off);
    }
    __syncthreads();

    int wm = (warp >> 2) * 64, wn = (warp & 3) * 32;
    uint32_t rs_b = smem_u32(rs), ks_b = smem_u32(ks);
    uint32_t vs_b = smem_u32(vs), ss_b = smem_u32(ss);
    uint32_t a_off = rs_b + (uint32_t)(((wm + ((lane >> 3) & 1) * 8 + lane7) * RSTR
                                      + ((lane >> 4) & 1) * 8) * 2);
    uint32_t b_off = ks_b + (uint32_t)(((wn + ((lane >> 4) & 1) * 8 + lane7) * RSTR
                                      + ((lane >> 3) & 1) * 8) * 2);
    float acc[4][4][4];
#pragma unroll
    for (int i = 0; i < 4; i++)
#pragma unroll
        for (int j = 0; j < 4; j++)
#pragma unroll
            for (int e = 0; e < 4; e++) acc[i][j][e] = 0.f;
#pragma unroll
    for (int kb = 0; kb < 4; kb++) {
        unsigned af[4][4], bf[8];
#pragma unroll
        for (int i = 0; i < 4; i++)
            ldsm4(af[i], a_off + i * (16 * RSTR * 2) + kb * 32);
        ldsm4(&bf[0], b_off + kb * 32);
        ldsm4(&bf[4], b_off + 16 * RSTR * 2 + kb * 32);
#pragma unroll
        for (int i = 0; i < 4; i++)
#pragma unroll
            for (int j = 0; j < 4; j++)
                mma_f16(acc[i][j], af[i], &bf[j * 2]);
    }

    float logw = -expf(tdcy[h]);
    float u    =  expf(tfirst[h]);
#pragma unroll
    for (int i = 0; i < 4; i++) {
#pragma unroll
        for (int j = 0; j < 4; j++) {
            int ri = wm + i * 16 + r0;
            int cj = wn + j * 8 + c0 * 2;
#pragma unroll
            for (int e = 0; e < 4; e++) {
                int rr = ri + (e >> 1) * 8;
                int cc = cj + (e & 1);
                float m;
                if (rr > cc)       m = expf(logw * (float)(rr - cc - 1));
                else if (rr == cc) m = u;
                else               m = 0.f;
                ss[rr * SSTR + cc] = __float2half(acc[i][j][e] * m);
            }
        }
    }
    __syncthreads();

    int wm2 = (warp >> 2) * 64, wn2 = (warp & 3) * 16;
    uint32_t a2 = ss_b + (uint32_t)(((wm2 + ((lane >> 3) & 1) * 8 + lane7) * SSTR
                                   + ((lane >> 4) & 1) * 8) * 2);
    uint32_t bt = vs_b + (uint32_t)(((((lane >> 3) & 1) * 8 + lane7) * RSTR
                                   + wn2 + ((lane >> 4) & 1) * 8) * 2);
    float acc2[4][2][4];
#pragma unroll
    for (int i = 0; i < 4; i++)
#pragma unroll
        for (int j = 0; j < 2; j++)
#pragma unroll
            for (int e = 0; e < 4; e++) acc2[i][j][e] = 0.f;
#pragma unroll
    for (int kb = 0; kb < 8; kb++) {
        unsigned af[4][4], bf[4];
#pragma unroll
        for (int i = 0; i < 4; i++)
            ldsm4(af[i], a2 + i * (16 * SSTR * 2) + kb * 32);
        ldsm4t(bf, bt + kb * (16 * RSTR * 2));
#pragma unroll
        for (int i = 0; i < 4; i++)
#pragma unroll
            for (int j = 0; j < 2; j++)
                mma_f16(acc2[i][j], af[i], &bf[j * 2]);
    }
#pragma unroll
    for (int i = 0; i < 4; i++) {
        int row = wm2 + i * 16 + r0;
        size_t o = ((size_t)(b * SEQ + chunk * CK + row)) * DM + h * 64;
#pragma unroll
        for (int j = 0; j < 2; j++) {
            int col = wn2 + j * 8 + c0 * 2;
            *(float2*)(g_att + o + col) = make_float2(acc2[i][j][0], acc2[i][j][1]);
            *(float2*)(g_att + o + (size_t)8 * DM + col) = make_float2(acc2[i][j][2], acc2[i][j][3]);
        }
    }
}

// ---------------- scan decomposition ----------------
__global__ void kv_kernel(const float* __restrict__ tdcy)
{
    int c = blockIdx.x, bh = blockIdx.y;
    int h = bh & 31, b = bh >> 5;
    int tid = threadIdx.x;
    __shared__ float bufA[32][68];
    __shared__ float bufB[32][68];
    float logw = -expf(tdcy[h]);
    int lrow = tid >> 3, lcol = (tid & 7) * 8;
    int td = (tid >> 4) * 4, te2 = (tid & 15) * 4;
    size_t base = ((size_t)(b*SEQ + c*CK)) * DM + h * 64;
    float sacc[4][4] = {};
    for (int s4 = 0; s4 < 4; s4++) {
        int j = s4 * 32 + lrow;
        float wk = expf(logw * (float)(127 - j));
        const float* ksrc = g_k + base + (size_t)j * DM + lcol;
        const float* vsrc = g_v + base + (size_t)j * DM + lcol;
        float4 k0 = *(const float4*)ksrc;
        float4 k1 = *(const float4*)(ksrc + 4);
        float4 w0 = *(const float4*)vsrc;
        float4 w1 = *(const float4*)(vsrc + 4);
        k0.x *= wk; k0.y *= wk; k0.z *= wk; k0.w *= wk;
        k1.x *= wk; k1.y *= wk; k1.z *= wk; k1.w *= wk;
        *(float4*)&bufA[lrow][lcol]     = k0;
        *(float4*)&bufA[lrow][lcol + 4] = k1;
        *(float4*)&bufB[lrow][lcol]     = w0;
        *(float4*)&bufB[lrow][lcol + 4] = w1;
        __syncthreads();
#pragma unroll 4
        for (int jj = 0; jj < 32; jj++) {
            float4 ka = *(const float4*)&bufA[jj][td];
            float4 vb = *(const float4*)&bufB[jj][te2];
            float ar[4] = {ka.x,ka.y,ka.z,ka.w};
            float br[4] = {vb.x,vb.y,vb.z,vb.w};
#pragma unroll
            for (int x = 0; x < 4; x++)
#pragma unroll
                for (int y = 0; y < 4; y++)
                    sacc[x][y] += ar[x] * br[y];
        }
        __syncthreads();
    }
    size_t obase = ((size_t)bh * NC + c) * 4096;
#pragma unroll
    for (int x = 0; x < 4; x++)
#pragma unroll
        for (int y = 0; y < 4; y++)
            g_kv[obase + (size_t)(td + x) * 64 + te2 + y] = sacc[x][y];
}

__global__ void combine_kernel(const float* __restrict__ tdcy,
                               float* __restrict__ state_out)
{
    int bh = blockIdx.x;
    int h = bh & 31;
    int tid = threadIdx.x;
    float wC = expf(-expf(tdcy[h]) * 128.f);
    float st[16];
#pragma unroll
    for (int q = 0; q < 16; q++) st[q] = 0.f;
    size_t base = (size_t)bh * NC * 4096;
    for (int c = 0; c < NC; c++) {
        size_t off = base + (size_t)c * 4096;
#pragma unroll
        for (int q = 0; q < 16; q++) {
            size_t idx = off + q * 256 + tid;
            g_state[idx] = st[q];
            st[q] = st[q] * wC + g_kv[idx];
        }
    }
#pragma unroll
    for (int q = 0; q < 16; q++)
        state_out[(size_t)bh * 4096 + q * 256 + tid] = st[q];
}

// ---------------- bias + per-head LN fused: writes g_atth directly --------
__global__ void bias_lnx_kernel(const float* __restrict__ tdcy,
                                const float* __restrict__ lsc,
                                const float* __restrict__ lbi)
{
    int c = blockIdx.x, bh = blockIdx.y;
    int h = bh & 31, b = bh >> 5;
    int tid = threadIdx.x;
    __shared__ float rs[64][132];
    __shared__ float ss[64][68];
    {
        int lrow = tid >> 1, lc = (tid & 1) * 32;
        size_t rbase = ((size_t)(b*SEQ + c*CK + lrow)) * DM + h * 64 + lc;
#pragma unroll
        for (int m = 0; m < 8; m++) {
            float4 rv = *(const float4*)(g_r + rbase + m * 4);
            int d = lc + m * 4;
            rs[d+0][lrow] = rv.x; rs[d+1][lrow] = rv.y;
            rs[d+2][lrow] = rv.z; rs[d+3][lrow] = rv.w;
        }
        size_t sbase = ((size_t)bh * NC + c) * 4096;
#pragma unroll
        for (int q = 0; q < 16; q++) {
            int idx = q * 256 + tid;
            ss[idx >> 6][idx & 63] = g_state[sbase + idx];
        }
    }
    __syncthreads();
    int ty = tid >> 3, tx = tid & 7;
    float acc[4][8] = {};
#pragma unroll 4
    for (int d = 0; d < 64; d++) {
        float4 a  = *(const float4*)&rs[d][ty * 4];
        float4 b0 = *(const float4*)&ss[d][tx * 8];
        float4 b1 = *(const float4*)&ss[d][tx * 8 + 4];
        float ar[4] = {a.x,a.y,a.z,a.w};
        float br[8] = {b0.x,b0.y,b0.z,b0.w,b1.x,b1.y,b1.z,b1.w};
#pragma unroll
        for (int x = 0; x < 4; x++)
#pragma unroll
            for (int e = 0; e < 8; e++)
                acc[x][e] += ar[x] * br[e];
    }
    float logw = -expf(tdcy[h]);
    size_t obase = ((size_t)(b*SEQ + c*CK)) * DM + h * 64;
#pragma unroll
    for (int x = 0; x < 4; x++) {
        int i = ty * 4 + x;
        float wi = expf(logw * (float)i);
        const float* src = g_att + obase + (size_t)i * DM + tx * 8;
        float v[8];
        float4 o0 = *(const float4*)src;
        float4 o1 = *(const float4*)(src + 4);
        v[0] = o0.x + wi * acc[x][0]; v[1] = o0.y + wi * acc[x][1];
        v[2] = o0.z + wi * acc[x][2]; v[3] = o0.w + wi * acc[x][3];
        v[4] = o1.x + wi * acc[x][4]; v[5] = o1.y + wi * acc[x][5];
        v[6] = o1.z + wi * acc[x][6]; v[7] = o1.w + wi * acc[x][7];
        float s = 0.f, q = 0.f;
#pragma unroll
        for (int e = 0; e < 8; e++) { s += v[e]; q += v[e] * v[e]; }
#pragma unroll
        for (int o = 4; o > 0; o >>= 1) {
            s += __shfl_xor_sync(0xffffffffu, s, o);
            q += __shfl_xor_sync(0xffffffffu, q, o);
        }
        float mu  = s * (1.f / 64.f);
        float inv = rsqrtf(q * (1.f / 64.f) - mu * mu + 1e-5f);
        __half2 hv[4];
#pragma unroll
        for (int e = 0; e < 4; e++) {
            int c0i = h * 64 + tx * 8 + e * 2;
            float y0 = (v[e*2]   - mu) * inv * lsc[c0i]     + lbi[c0i];
            float y1 = (v[e*2+1] - mu) * inv * lsc[c0i + 1] + lbi[c0i + 1];
            hv[e] = __floats2half2_rn(y0, y1);
        }
        *(uint4*)(g_atth + obase + (size_t)i * DM + tx * 8) = *(uint4*)hv;
    }
}

// ---------------- launch ----------------
extern "C" void kernel_launch(void* const* d_in, const int* in_sizes, int n_in,
                              void* d_out, int out_size)
{
    const float* inputs = (const float*)d_in[0];
    const float* tmr    = (const float*)d_in[1];
    const float* tmk    = (const float*)d_in[2];
    const float* tmv    = (const float*)d_in[3];
    const float* Wk     = (const float*)d_in[4];
    const float* Wv     = (const float*)d_in[5];
    const float* Wr     = (const float*)d_in[6];
    const float* Wo     = (const float*)d_in[7];
    const float* tdcy   = (const float*)d_in[8];
    const float* tfirst = (const float*)d_in[9];
    const float* ln1s   = (const float*)d_in[10];
    const float* ln1b   = (const float*)d_in[11];
    const float* lnxs   = (const float*)d_in[12];
    const float* lnxb   = (const float*)d_in[13];

    float* out0      = (float*)d_out;
    float* out_xlast = out0 + (size_t)BZ * SEQ * DM;
    float* out_state = out_xlast + (size_t)BZ * DM;

    const int GSMEM = STAGES * STG_BYTES;   // 61440 B
    cudaFuncSetAttribute(tgemm_kernel<0>, cudaFuncAttributeMaxDynamicSharedMemorySize, GSMEM);
    cudaFuncSetAttribute(tgemm_kernel<1>, cudaFuncAttributeMaxDynamicSharedMemorySize, GSMEM);
    cudaFuncSetAttribute(tgemm_kernel<2>, cudaFuncAttributeMaxDynamicSharedMemorySize, GSMEM);
    cudaFuncSetAttribute(tgemm_kernel<3>, cudaFuncAttributeMaxDynamicSharedMemorySize, GSMEM);
    cudaFuncSetAttribute(att_kernel,      cudaFuncAttributeMaxDynamicSharedMemorySize, ATT_SMEM);

    __half* wtr; __half* wtk; __half* wtv; __half* wto;
    cudaGetSymbolAddress((void**)&wtr, g_wtr);
    cudaGetSymbolAddress((void**)&wtk, g_wtk);
    cudaGetSymbolAddress((void**)&wtv, g_wtv);
    cudaGetSymbolAddress((void**)&wto, g_wto);

    transpose4_kernel<<<dim3(64, 64, 4), dim3(32, 8)>>>(Wr, wtr, Wk, wtk, Wv, wtv, Wo, wto);
    lnmix_kernel<<<MROWS, 256>>>(inputs, ln1s, ln1b, tmr, tmk, tmv, out_xlast);

    dim3 g(DM / 128, MROWS / 128);
    tgemm_kernel<0><<<g, 256, GSMEM>>>(wtr, nullptr, nullptr);
    tgemm_kernel<1><<<g, 256, GSMEM>>>(wtk, nullptr, nullptr);
    tgemm_kernel<2><<<g, 256, GSMEM>>>(wtv, nullptr, nullptr);
    att_kernel<<<BZ * NC * NH, 256, ATT_SMEM>>>(tdcy, tfirst);
    kv_kernel<<<dim3(NC, BZ * NH), 256>>>(tdcy);
    combine_kernel<<<BZ * NH, 256>>>(tdcy, out_state);
    bias_lnx_kernel<<<dim3(NC, BZ * NH), 256>>>(tdcy, lnxs, lnxb);
    lnx_unused:;
    tgemm_kernel<3><<<g, 256, GSMEM>>>(wto, inputs, out0);
}

// round 16
// speedup vs baseline: 1.2923x; 1.0428x over previous
#include <cuda_runtime.h>
#include <cuda_fp16.h>
#include <cstdint>

#define SEQ   2048
#define DM    2048
#define NH    32
#define DH    64
#define CK    128
#define NC    16
#define BZ    4
#define MROWS (BZ*SEQ)   // 8192
#define BK    16
#define NKT   (DM/BK)    // 128
#define STAGES 5

// ---------------- scratch (device globals; no allocation) ----------------
__device__ __align__(256) __half g_rxh [BZ*SEQ*DM];
__device__ __align__(256) __half g_kxh [BZ*SEQ*DM];
__device__ __align__(256) __half g_vxh [BZ*SEQ*DM];
__device__ __align__(256) __half g_atth[BZ*SEQ*DM];
__device__ __align__(256) __half g_rh  [BZ*SEQ*DM];
__device__ __align__(256) __half g_kh  [BZ*SEQ*DM];
__device__ __align__(256) __half g_vh  [BZ*SEQ*DM];
__device__ float g_att[BZ*SEQ*DM];
__device__ float g_kv   [BZ*NH*NC*DH*DH];
__device__ float g_state[BZ*NH*NC*DH*DH];
__device__ __align__(256) __half g_wtr[DM*DM];
__device__ __align__(256) __half g_wtk[DM*DM];
__device__ __align__(256) __half g_wtv[DM*DM];
__device__ __align__(256) __half g_wto[DM*DM];

// ---------------- small PTX helpers ----------------
__device__ __forceinline__ uint32_t smem_u32(const void* p)
{
    uint32_t a;
    asm("{ .reg .u64 t; cvta.to.shared.u64 t, %1; cvt.u32.u64 %0, t; }" : "=r"(a) : "l"(p));
    return a;
}
template<int N> __device__ __forceinline__ void cp_wait()
{
    asm volatile("cp.async.wait_group %0;" :: "n"(N) : "memory");
}
__device__ __forceinline__ void cp16(uint32_t dst, const void* src)
{
    asm volatile("cp.async.cg.shared.global [%0], [%1], 16;" :: "r"(dst), "l"(src));
}
__device__ __forceinline__ void cp_commit()
{
    asm volatile("cp.async.commit_group;" ::: "memory");
}
__device__ __forceinline__ void mma_f16(float* c, const unsigned* a, const unsigned* b)
{
    asm volatile(
        "mma.sync.aligned.m16n8k16.row.col.f32.f16.f16.f32 "
        "{%0,%1,%2,%3}, {%4,%5,%6,%7}, {%8,%9}, {%0,%1,%2,%3};"
        : "+f"(c[0]), "+f"(c[1]), "+f"(c[2]), "+f"(c[3])
        : "r"(a[0]), "r"(a[1]), "r"(a[2]), "r"(a[3]),
          "r"(b[0]), "r"(b[1]));
}
__device__ __forceinline__ void ldsm4(unsigned* r, uint32_t addr)
{
    asm volatile("ldmatrix.sync.aligned.m8n8.x4.shared.b16 {%0,%1,%2,%3}, [%4];"
        : "=r"(r[0]), "=r"(r[1]), "=r"(r[2]), "=r"(r[3]) : "r"(addr));
}
__device__ __forceinline__ void ldsm4t(unsigned* r, uint32_t addr)
{
    asm volatile("ldmatrix.sync.aligned.m8n8.x4.trans.shared.b16 {%0,%1,%2,%3}, [%4];"
        : "=r"(r[0]), "=r"(r[1]), "=r"(r[2]), "=r"(r[3]) : "r"(addr));
}

// ---------------- fused LN + token-shift mixing (fp16 outputs) ------------
__global__ void lnmix_kernel(const float* __restrict__ x,
                             const float* __restrict__ sc,
                             const float* __restrict__ bi,
                             const float* __restrict__ tmr,
                             const float* __restrict__ tmk,
                             const float* __restrict__ tmv,
                             float* __restrict__ xlast)
{
    int row = blockIdx.x;
    int t   = row & (SEQ - 1);
    const float* xr = x + (size_t)row * DM;
    float cur[8], prv[8];
    float s0 = 0.f, q0 = 0.f, s1 = 0.f, q1 = 0.f;
#pragma unroll
    for (int i = 0; i < 8; i++) {
        int c = threadIdx.x + i * 256;
        float v = xr[c];
        cur[i] = v; s0 += v; q0 += v * v;
        float u = t ? xr[c - DM] : 0.f;
        prv[i] = u; s1 += u; q1 += u * u;
    }
#pragma unroll
    for (int o = 16; o > 0; o >>= 1) {
        s0 += __shfl_xor_sync(0xffffffffu, s0, o);
        q0 += __shfl_xor_sync(0xffffffffu, q0, o);
        s1 += __shfl_xor_sync(0xffffffffu, s1, o);
        q1 += __shfl_xor_sync(0xffffffffu, q1, o);
    }
    __shared__ float rs0[8], rq0[8], rs1[8], rq1[8];
    int w = threadIdx.x >> 5;
    if ((threadIdx.x & 31) == 0) { rs0[w] = s0; rq0[w] = q0; rs1[w] = s1; rq1[w] = q1; }
    __syncthreads();
    s0 = 0.f; q0 = 0.f; s1 = 0.f; q1 = 0.f;
#pragma unroll
    for (int i = 0; i < 8; i++) { s0 += rs0[i]; q0 += rq0[i]; s1 += rs1[i]; q1 += rq1[i]; }
    float mu0  = s0 * (1.f / DM);
    float inv0 = rsqrtf(q0 * (1.f / DM) - mu0 * mu0 + 1e-5f);
    float mu1  = s1 * (1.f / DM);
    float inv1 = rsqrtf(q1 * (1.f / DM) - mu1 * mu1 + 1e-5f);
    bool last = (t == SEQ - 1);
#pragma unroll
    for (int i = 0; i < 8; i++) {
        int c = threadIdx.x + i * 256;
        float yc = (cur[i] - mu0) * inv0 * sc[c] + bi[c];
        float yp = t ? (prv[i] - mu1) * inv1 * sc[c] + bi[c] : 0.f;
        size_t off = (size_t)row * DM + c;
        float mr = tmr[c], mk = tmk[c], mv = tmv[c];
        g_rxh[off] = __float2half(yc * mr + (1.f - mr) * yp);
        g_kxh[off] = __float2half(yc * mk + (1.f - mk) * yp);
        g_vxh[off] = __float2half(yc * mv + (1.f - mv) * yp);
        if (last) xlast[(row >> 11) * DM + c] = yc;
    }
}

// ---------------- 4 weight transposes in one launch (fp16 outputs) --------
__global__ void transpose4_kernel(const float* __restrict__ s0, __half* __restrict__ d0,
                                  const float* __restrict__ s1, __half* __restrict__ d1,
                                  const float* __restrict__ s2, __half* __restrict__ d2,
                                  const float* __restrict__ s3, __half* __restrict__ d3)
{
    const float* src; __half* dst;
    switch (blockIdx.z) {
        case 0:  src = s0; dst = d0; break;
        case 1:  src = s1; dst = d1; break;
        case 2:  src = s2; dst = d2; break;
        default: src = s3; dst = d3; break;
    }
    __shared__ float t[32][33];
    int bx = blockIdx.x * 32, by = blockIdx.y * 32;
#pragma unroll
    for (int i = 0; i < 4; i++)
        t[threadIdx.y + i * 8][threadIdx.x] =
            src[(size_t)(by + threadIdx.y + i * 8) * DM + bx + threadIdx.x];
    __syncthreads();
#pragma unroll
    for (int i = 0; i < 4; i++)
        dst[(size_t)(bx + threadIdx.y + i * 8) * DM + by + threadIdx.x] =
            __float2half(t[threadIdx.x][threadIdx.y + i * 8]);
}

// ---------------- fp16 mma.sync GEMM (R11 layout; 5-stage, sync every 2) --
// MODE 0-2 write fp16 only (r/k/v consumed downstream in fp16); MODE 3 fp32+Add
#define HSTRIDE 24                        // halves per smem row (16 data + 8 pad)
#define STG_BYTES (2 * 128 * HSTRIDE * 2) // A tile + B tile per stage = 12288 B

template<int MODE>
__global__ void __launch_bounds__(256, 2) tgemm_kernel(const __half* __restrict__ Bt,
                                                       const float* __restrict__ Add,
                                                       float* __restrict__ Out)
{
    const __half* A;
    if constexpr (MODE == 0) A = g_rxh;
    else if constexpr (MODE == 1) A = g_kxh;
    else if constexpr (MODE == 2) A = g_vxh;
    else A = g_atth;

    extern __shared__ char smem[];
    uint32_t sb = smem_u32(smem);
    int tid = threadIdx.x, lane = tid & 31, warp = tid >> 5;
    int r0 = lane >> 2, c0 = lane & 3;
    int wm = (warp >> 2) * 64, wn = (warp & 3) * 32;
    int bm = blockIdx.y * 128, bn = blockIdx.x * 128;

    const __half* Ag = A  + (size_t)bm * DM;
    const __half* Bg = Bt + (size_t)bn * DM;

    int lane7 = lane & 7;
    uint32_t a_off = (uint32_t)(((wm + ((lane >> 3) & 1) * 8 + lane7) * HSTRIDE
                                + ((lane >> 4) & 1) * 8) * 2);
    uint32_t b_off = (uint32_t)(((wn + ((lane >> 4) & 1) * 8 + lane7) * HSTRIDE
                                + ((lane >> 3) & 1) * 8) * 2);

    // copy: two threads per row, 16B each (R11 champion mapping)
    int cm = tid >> 1, cq = (tid & 1) * 8;
    auto copy_stage = [&](int buf, int kt) {
        uint32_t sA = sb + buf * STG_BYTES;
        uint32_t sB = sA + 128 * HSTRIDE * 2;
        uint32_t off = cm * (HSTRIDE * 2) + cq * 2;
        cp16(sA + off, Ag + kt * BK + (size_t)cm * DM + cq);
        cp16(sB + off, Bg + kt * BK + (size_t)cm * DM + cq);
        cp_commit();
    };

    float acc[4][4][4];
#pragma unroll
    for (int i = 0; i < 4; i++)
#pragma unroll
        for (int j = 0; j < 4; j++)
#pragma unroll
            for (int e = 0; e < 4; e++) acc[i][j][e] = 0.f;

    copy_stage(0, 0);
    copy_stage(1, 1);
    copy_stage(2, 2);
    cp_wait<1>();       // buffers 0,1 complete
    __syncthreads();

    // prefetch distance 3, 5 buffers; sync every 2 iterations (see R15)
    int buf = 0, cbuf = 3;
    for (int kt = 0; kt < NKT; kt++) {
        if (kt && !(kt & 1)) {
            cp_wait<1>();
            __syncthreads();
        }
        uint32_t sA = sb + buf * STG_BYTES;
        uint32_t sB = sA + 128 * HSTRIDE * 2;
        unsigned af[4][4], bf[8];
#pragma unroll
        for (int i = 0; i < 4; i++)
            ldsm4(af[i], sA + a_off + i * (16 * HSTRIDE * 2));
        ldsm4(&bf[0], sB + b_off);
        ldsm4(&bf[4], sB + b_off + 16 * HSTRIDE * 2);
#pragma unroll
        for (int i = 0; i < 4; i++)
#pragma unroll
            for (int j = 0; j < 4; j++)
                mma_f16(acc[i][j], af[i], &bf[j * 2]);
        if (kt + 3 < NKT) copy_stage(cbuf, kt + 3);
        else              cp_commit();     // keep one group per iteration
        buf  = (buf  == STAGES - 1) ? 0 : buf + 1;
        cbuf = (cbuf == STAGES - 1) ? 0 : cbuf + 1;
    }

#pragma unroll
    for (int i = 0; i < 4; i++) {
        int row = bm + wm + i * 16 + r0;
#pragma unroll
        for (int j = 0; j < 4; j++) {
            int col = bn + wn + j * 8 + c0 * 2;
            size_t o0 = (size_t)row * DM + col;
            size_t o1 = (size_t)(row + 8) * DM + col;
            float2 v0 = make_float2(acc[i][j][0], acc[i][j][1]);
            float2 v1 = make_float2(acc[i][j][2], acc[i][j][3]);
            if constexpr (MODE == 3) {
                float2 a0 = *(const float2*)(Add + o0);
                float2 a1 = *(const float2*)(Add + o1);
                v0.x += a0.x; v0.y += a0.y;
                v1.x += a1.x; v1.y += a1.y;
                *(float2*)(Out + o0) = v0;
                *(float2*)(Out + o1) = v1;
            } else {
                __half* Ch = (MODE == 0) ? g_rh : (MODE == 1) ? g_kh : g_vh;
                *(__half2*)(Ch + o0) = __floats2half2_rn(v0.x, v0.y);
                *(__half2*)(Ch + o1) = __floats2half2_rn(v1.x, v1.y);
            }
        }
    }
}

// ---------------- fused attention: sep = ((r@k^T)*mask) @ v ---------------
#define RSTR 72    // halves per row, r/k/v tiles (64 data + 8 pad)
#define SSTR 136   // halves per row, S tile (128 data + 8 pad)
#define ATT_SMEM (3 * 128 * RSTR * 2 + 128 * SSTR * 2)   // 90112 B

__global__ void __launch_bounds__(256, 2) att_kernel(const float* __restrict__ tdcy,
                                                     const float* __restrict__ tfirst)
{
    int bch = blockIdx.x;
    int h = bch & 31;
    int chunk = (bch >> 5) & 15;
    int b = bch >> 9;
    extern __shared__ char smem[];
    __half* rs = (__half*)smem;
    __half* ks = rs + 128 * RSTR;
    __half* vs = ks + 128 * RSTR;
    __half* ss = vs + 128 * RSTR;
    int tid = threadIdx.x, lane = tid & 31, warp = tid >> 5;
    int lane7 = lane & 7;
    int r0 = lane >> 2, c0 = lane & 3;

    size_t gbase = ((size_t)(b * SEQ + chunk * CK)) * DM + h * 64;
#pragma unroll
    for (int q = 0; q < 4; q++) {
        int idx = q * 256 + tid;
        int row = idx >> 3, c8 = (idx & 7) * 8;
        size_t off = gbase + (size_t)row * DM + c8;
        *(uint4*)&rs[row * RSTR + c8] = *(const uint4*)(g_rh + off);
        *(uint4*)&ks[row * RSTR + c8] = *(const uint4*)(g_kh + off);
        *(uint4*)&vs[row * RSTR + c8] = *(const uint4*)(g_vh + off);
    }
    __syncthreads();

    int wm = (warp >> 2) * 64, wn = (warp & 3) * 32;
    uint32_t rs_b = smem_u32(rs), ks_b = smem_u32(ks);
    uint32_t vs_b = smem_u32(vs), ss_b = smem_u32(ss);
    uint32_t a_off = rs_b + (uint32_t)(((wm + ((lane >> 3) & 1) * 8 + lane7) * RSTR
                                      + ((lane >> 4) & 1) * 8) * 2);
    uint32_t b_off = ks_b + (uint32_t)(((wn + ((lane >> 4) & 1) * 8 + lane7) * RSTR
                                      + ((lane >> 3) & 1) * 8) * 2);
    float acc[4][4][4];
#pragma unroll
    for (int i = 0; i < 4; i++)
#pragma unroll
        for (int j = 0; j < 4; j++)
#pragma unroll
            for (int e = 0; e < 4; e++) acc[i][j][e] = 0.f;
#pragma unroll
    for (int kb = 0; kb < 4; kb++) {
        unsigned af[4][4], bf[8];
#pragma unroll
        for (int i = 0; i < 4; i++)
            ldsm4(af[i], a_off + i * (16 * RSTR * 2) + kb * 32);
        ldsm4(&bf[0], b_off + kb * 32);
        ldsm4(&bf[4], b_off + 16 * RSTR * 2 + kb * 32);
#pragma unroll
        for (int i = 0; i < 4; i++)
#pragma unroll
            for (int j = 0; j < 4; j++)
                mma_f16(acc[i][j], af[i], &bf[j * 2]);
    }

    float logw = -expf(tdcy[h]);
    float u    =  expf(tfirst[h]);
#pragma unroll
    for (int i = 0; i < 4; i++) {
#pragma unroll
        for (int j = 0; j < 4; j++) {
            int ri = wm + i * 16 + r0;
            int cj = wn + j * 8 + c0 * 2;
#pragma unroll
            for (int e = 0; e < 4; e++) {
                int rr = ri + (e >> 1) * 8;
                int cc = cj + (e & 1);
                float m;
                if (rr > cc)       m = expf(logw * (float)(rr - cc - 1));
                else if (rr == cc) m = u;
                else               m = 0.f;
                ss[rr * SSTR + cc] = __float2half(acc[i][j][e] * m);
            }
        }
    }
    __syncthreads();

    int wm2 = (warp >> 2) * 64, wn2 = (warp & 3) * 16;
    uint32_t a2 = ss_b + (uint32_t)(((wm2 + ((lane >> 3) & 1) * 8 + lane7) * SSTR
                                   + ((lane >> 4) & 1) * 8) * 2);
    uint32_t bt = vs_b + (uint32_t)(((((lane >> 3) & 1) * 8 + lane7) * RSTR
                                   + wn2 + ((lane >> 4) & 1) * 8) * 2);
    float acc2[4][2][4];
#pragma unroll
    for (int i = 0; i < 4; i++)
#pragma unroll
        for (int j = 0; j < 2; j++)
#pragma unroll
            for (int e = 0; e < 4; e++) acc2[i][j][e] = 0.f;
#pragma unroll
    for (int kb = 0; kb < 8; kb++) {
        unsigned af[4][4], bf[4];
#pragma unroll
        for (int i = 0; i < 4; i++)
            ldsm4(af[i], a2 + i * (16 * SSTR * 2) + kb * 32);
        ldsm4t(bf, bt + kb * (16 * RSTR * 2));
#pragma unroll
        for (int i = 0; i < 4; i++)
#pragma unroll
            for (int j = 0; j < 2; j++)
                mma_f16(acc2[i][j], af[i], &bf[j * 2]);
    }
#pragma unroll
    for (int i = 0; i < 4; i++) {
        int row = wm2 + i * 16 + r0;
        size_t o = ((size_t)(b * SEQ + chunk * CK + row)) * DM + h * 64;
#pragma unroll
        for (int j = 0; j < 2; j++) {
            int col = wn2 + j * 8 + c0 * 2;
            *(float2*)(g_att + o + col) = make_float2(acc2[i][j][0], acc2[i][j][1]);
            *(float2*)(g_att + o + (size_t)8 * DM + col) = make_float2(acc2[i][j][2], acc2[i][j][3]);
        }
    }
}

// ---------------- scan decomposition (k/v consumed in fp16) ----------------
__global__ void kv_kernel(const float* __restrict__ tdcy)
{
    int c = blockIdx.x, bh = blockIdx.y;
    int h = bh & 31, b = bh >> 5;
    int tid = threadIdx.x;
    __shared__ float bufA[32][68];
    __shared__ float bufB[32][68];
    float logw = -expf(tdcy[h]);
    int lrow = tid >> 3, lcol = (tid & 7) * 8;
    int td = (tid >> 4) * 4, te2 = (tid & 15) * 4;
    size_t base = ((size_t)(b*SEQ + c*CK)) * DM + h * 64;
    float sacc[4][4] = {};
    for (int s4 = 0; s4 < 4; s4++) {
        int j = s4 * 32 + lrow;
        float wk = expf(logw * (float)(127 - j));
        size_t off = base + (size_t)j * DM + lcol;
        uint4 kraw = *(const uint4*)(g_kh + off);
        uint4 vraw = *(const uint4*)(g_vh + off);
        const __half2* kh = (const __half2*)&kraw;
        const __half2* vh = (const __half2*)&vraw;
#pragma unroll
        for (int m = 0; m < 4; m++) {
            float2 kf = __half22float2(kh[m]);
            float2 vf = __half22float2(vh[m]);
            bufA[lrow][lcol + m*2]     = kf.x * wk;
            bufA[lrow][lcol + m*2 + 1] = kf.y * wk;
            bufB[lrow][lcol + m*2]     = vf.x;
            bufB[lrow][lcol + m*2 + 1] = vf.y;
        }
        __syncthreads();
#pragma unroll 4
        for (int jj = 0; jj < 32; jj++) {
            float4 ka = *(const float4*)&bufA[jj][td];
            float4 vb = *(const float4*)&bufB[jj][te2];
            float ar[4] = {ka.x,ka.y,ka.z,ka.w};
            float br[4] = {vb.x,vb.y,vb.z,vb.w};
#pragma unroll
            for (int x = 0; x < 4; x++)
#pragma unroll
                for (int y = 0; y < 4; y++)
                    sacc[x][y] += ar[x] * br[y];
        }
        __syncthreads();
    }
    size_t obase = ((size_t)bh * NC + c) * 4096;
#pragma unroll
    for (int x = 0; x < 4; x++)
#pragma unroll
        for (int y = 0; y < 4; y++)
            g_kv[obase + (size_t)(td + x) * 64 + te2 + y] = sacc[x][y];
}

__global__ void combine_kernel(const float* __restrict__ tdcy,
                               float* __restrict__ state_out)
{
    int bh = blockIdx.x;
    int h = bh & 31;
    int tid = threadIdx.x;
    float wC = expf(-expf(tdcy[h]) * 128.f);
    float st[16];
#pragma unroll
    for (int q = 0; q < 16; q++) st[q] = 0.f;
    size_t base = (size_t)bh * NC * 4096;
    for (int c = 0; c < NC; c++) {
        size_t off = base + (size_t)c * 4096;
#pragma unroll
        for (int q = 0; q < 16; q++) {
            size_t idx = off + q * 256 + tid;
            g_state[idx] = st[q];
            st[q] = st[q] * wC + g_kv[idx];
        }
    }
#pragma unroll
    for (int q = 0; q < 16; q++)
        state_out[(size_t)bh * 4096 + q * 256 + tid] = st[q];
}

// ---------------- bias + per-head LN fused (r consumed in fp16) ------------
__global__ void bias_lnx_kernel(const float* __restrict__ tdcy,
                                const float* __restrict__ lsc,
                                const float* __restrict__ lbi)
{
    int c = blockIdx.x, bh = blockIdx.y;
    int h = bh & 31, b = bh >> 5;
    int tid = threadIdx.x;
    __shared__ float rs[64][132];
    __shared__ float ss[64][68];
    {
        int lrow = tid >> 1, lc = (tid & 1) * 32;
        size_t rbase = ((size_t)(b*SEQ + c*CK + lrow)) * DM + h * 64 + lc;
#pragma unroll
        for (int m = 0; m < 4; m++) {
            uint4 raw = *(const uint4*)(g_rh + rbase + m * 8);
            const __half2* rh = (const __half2*)&raw;
#pragma unroll
            for (int e = 0; e < 4; e++) {
                float2 f = __half22float2(rh[e]);
                int d = lc + m * 8 + e * 2;
                rs[d][lrow]     = f.x;
                rs[d + 1][lrow] = f.y;
            }
        }
        size_t sbase = ((size_t)bh * NC + c) * 4096;
#pragma unroll
        for (int q = 0; q < 16; q++) {
            int idx = q * 256 + tid;
            ss[idx >> 6][idx & 63] = g_state[sbase + idx];
        }
    }
    __syncthreads();
    int ty = tid >> 3, tx = tid & 7;
    float acc[4][8] = {};
#pragma unroll 4
    for (int d = 0; d < 64; d++) {
        float4 a  = *(const float4*)&rs[d][ty * 4];
        float4 b0 = *(const float4*)&ss[d][tx * 8];
        float4 b1 = *(const float4*)&ss[d][tx * 8 + 4];
        float ar[4] = {a.x,a.y,a.z,a.w};
        float br[8] = {b0.x,b0.y,b0.z,b0.w,b1.x,b1.y,b1.z,b1.w};
#pragma unroll
        for (int x = 0; x < 4; x++)
#pragma unroll
            for (int e = 0; e < 8; e++)
                acc[x][e] += ar[x] * br[e];
    }
    float logw = -expf(tdcy[h]);
    size_t obase = ((size_t)(b*SEQ + c*CK)) * DM + h * 64;
#pragma unroll
    for (int x = 0; x < 4; x++) {
        int i = ty * 4 + x;
        float wi = expf(logw * (float)i);
        const float* src = g_att + obase + (size_t)i * DM + tx * 8;
        float v[8];
        float4 o0 = *(const float4*)src;
        float4 o1 = *(const float4*)(src + 4);
        v[0] = o0.x + wi * acc[x][0]; v[1] = o0.y + wi * acc[x][1];
        v[2] = o0.z + wi * acc[x][2]; v[3] = o0.w + wi * acc[x][3];
        v[4] = o1.x + wi * acc[x][4]; v[5] = o1.y + wi * acc[x][5];
        v[6] = o1.z + wi * acc[x][6]; v[7] = o1.w + wi * acc[x][7];
        float s = 0.f, q = 0.f;
#pragma unroll
        for (int e = 0; e < 8; e++) { s += v[e]; q += v[e] * v[e]; }
#pragma unroll
        for (int o = 4; o > 0; o >>= 1) {
            s += __shfl_xor_sync(0xffffffffu, s, o);
            q += __shfl_xor_sync(0xffffffffu, q, o);
        }
        float mu  = s * (1.f / 64.f);
        float inv = rsqrtf(q * (1.f / 64.f) - mu * mu + 1e-5f);
        __half2 hv[4];
#pragma unroll
        for (int e = 0; e < 4; e++) {
            int c0i = h * 64 + tx * 8 + e * 2;
            float y0 = (v[e*2]   - mu) * inv * lsc[c0i]     + lbi[c0i];
            float y1 = (v[e*2+1] - mu) * inv * lsc[c0i + 1] + lbi[c0i + 1];
            hv[e] = __floats2half2_rn(y0, y1);
        }
        *(uint4*)(g_atth + obase + (size_t)i * DM + tx * 8) = *(uint4*)hv;
    }
}

// ---------------- launch ----------------
extern "C" void kernel_launch(void* const* d_in, const int* in_sizes, int n_in,
                              void* d_out, int out_size)
{
    const float* inputs = (const float*)d_in[0];
    const float* tmr    = (const float*)d_in[1];
    const float* tmk    = (const float*)d_in[2];
    const float* tmv    = (const float*)d_in[3];
    const float* Wk     = (const float*)d_in[4];
    const float* Wv     = (const float*)d_in[5];
    const float* Wr     = (const float*)d_in[6];
    const float* Wo     = (const float*)d_in[7];
    const float* tdcy   = (const float*)d_in[8];
    const float* tfirst = (const float*)d_in[9];
    const float* ln1s   = (const float*)d_in[10];
    const float* ln1b   = (const float*)d_in[11];
    const float* lnxs   = (const float*)d_in[12];
    const float* lnxb   = (const float*)d_in[13];

    float* out0      = (float*)d_out;
    float* out_xlast = out0 + (size_t)BZ * SEQ * DM;
    float* out_state = out_xlast + (size_t)BZ * DM;

    const int GSMEM = STAGES * STG_BYTES;   // 61440 B
    cudaFuncSetAttribute(tgemm_kernel<0>, cudaFuncAttributeMaxDynamicSharedMemorySize, GSMEM);
    cudaFuncSetAttribute(tgemm_kernel<1>, cudaFuncAttributeMaxDynamicSharedMemorySize, GSMEM);
    cudaFuncSetAttribute(tgemm_kernel<2>, cudaFuncAttributeMaxDynamicSharedMemorySize, GSMEM);
    cudaFuncSetAttribute(tgemm_kernel<3>, cudaFuncAttributeMaxDynamicSharedMemorySize, GSMEM);
    cudaFuncSetAttribute(att_kernel,      cudaFuncAttributeMaxDynamicSharedMemorySize, ATT_SMEM);

    __half* wtr; __half* wtk; __half* wtv; __half* wto;
    cudaGetSymbolAddress((void**)&wtr, g_wtr);
    cudaGetSymbolAddress((void**)&wtk, g_wtk);
    cudaGetSymbolAddress((void**)&wtv, g_wtv);
    cudaGetSymbolAddress((void**)&wto, g_wto);

    transpose4_kernel<<<dim3(64, 64, 4), dim3(32, 8)>>>(Wr, wtr, Wk, wtk, Wv, wtv, Wo, wto);
    lnmix_kernel<<<MROWS, 256>>>(inputs, ln1s, ln1b, tmr, tmk, tmv, out_xlast);

    dim3 g(DM / 128, MROWS / 128);
    tgemm_kernel<0><<<g, 256, GSMEM>>>(wtr, nullptr, nullptr);
    tgemm_kernel<1><<<g, 256, GSMEM>>>(wtk, nullptr, nullptr);
    tgemm_kernel<2><<<g, 256, GSMEM>>>(wtv, nullptr, nullptr);
    att_kernel<<<BZ * NC * NH, 256, ATT_SMEM>>>(tdcy, tfirst);
    kv_kernel<<<dim3(NC, BZ * NH), 256>>>(tdcy);
    combine_kernel<<<BZ * NH, 256>>>(tdcy, out_state);
    bias_lnx_kernel<<<dim3(NC, BZ * NH), 256>>>(tdcy, lnxs, lnxb);
    tgemm_kernel<3><<<g, 256, GSMEM>>>(wto, inputs, out0);
}

// round 17
// speedup vs baseline: 1.3562x; 1.0494x over previous
#include <cuda_runtime.h>
#include <cuda_fp16.h>
#include <cstdint>

#define SEQ   2048
#define DM    2048
#define NH    32
#define DH    64
#define CK    128
#define NC    16
#define BZ    4
#define MROWS (BZ*SEQ)   // 8192
#define BK    16
#define NKT   (DM/BK)    // 128
#define STAGES 5

// ---------------- scratch (device globals; no allocation) ----------------
__device__ __align__(256) __half g_rxh [BZ*SEQ*DM];
__device__ __align__(256) __half g_kxh [BZ*SEQ*DM];
__device__ __align__(256) __half g_vxh [BZ*SEQ*DM];
__device__ __align__(256) __half g_atth[BZ*SEQ*DM];
__device__ __align__(256) __half g_rh  [BZ*SEQ*DM];
__device__ __align__(256) __half g_kh  [BZ*SEQ*DM];
__device__ __align__(256) __half g_vh  [BZ*SEQ*DM];
__device__ float g_att[BZ*SEQ*DM];
__device__ float g_kv   [BZ*NH*NC*DH*DH];
__device__ float g_state[BZ*NH*NC*DH*DH];
__device__ __align__(256) __half g_wtr[DM*DM];
__device__ __align__(256) __half g_wtk[DM*DM];
__device__ __align__(256) __half g_wtv[DM*DM];
__device__ __align__(256) __half g_wto[DM*DM];

// ---------------- small PTX helpers ----------------
__device__ __forceinline__ uint32_t smem_u32(const void* p)
{
    uint32_t a;
    asm("{ .reg .u64 t; cvta.to.shared.u64 t, %1; cvt.u32.u64 %0, t; }" : "=r"(a) : "l"(p));
    return a;
}
template<int N> __device__ __forceinline__ void cp_wait()
{
    asm volatile("cp.async.wait_group %0;" :: "n"(N) : "memory");
}
__device__ __forceinline__ void cp16(uint32_t dst, const void* src)
{
    asm volatile("cp.async.cg.shared.global [%0], [%1], 16;" :: "r"(dst), "l"(src));
}
__device__ __forceinline__ void cp_commit()
{
    asm volatile("cp.async.commit_group;" ::: "memory");
}
__device__ __forceinline__ void mma_f16(float* c, const unsigned* a, const unsigned* b)
{
    asm volatile(
        "mma.sync.aligned.m16n8k16.row.col.f32.f16.f16.f32 "
        "{%0,%1,%2,%3}, {%4,%5,%6,%7}, {%8,%9}, {%0,%1,%2,%3};"
        : "+f"(c[0]), "+f"(c[1]), "+f"(c[2]), "+f"(c[3])
        : "r"(a[0]), "r"(a[1]), "r"(a[2]), "r"(a[3]),
          "r"(b[0]), "r"(b[1]));
}
__device__ __forceinline__ void ldsm4(unsigned* r, uint32_t addr)
{
    asm volatile("ldmatrix.sync.aligned.m8n8.x4.shared.b16 {%0,%1,%2,%3}, [%4];"
        : "=r"(r[0]), "=r"(r[1]), "=r"(r[2]), "=r"(r[3]) : "r"(addr));
}
__device__ __forceinline__ void ldsm4t(unsigned* r, uint32_t addr)
{
    asm volatile("ldmatrix.sync.aligned.m8n8.x4.trans.shared.b16 {%0,%1,%2,%3}, [%4];"
        : "=r"(r[0]), "=r"(r[1]), "=r"(r[2]), "=r"(r[3]) : "r"(addr));
}

// ---------------- fused LN + token-shift mixing (fp16 outputs) ------------
__global__ void lnmix_kernel(const float* __restrict__ x,
                             const float* __restrict__ sc,
                             const float* __restrict__ bi,
                             const float* __restrict__ tmr,
                             const float* __restrict__ tmk,
                             const float* __restrict__ tmv,
                             float* __restrict__ xlast)
{
    int row = blockIdx.x;
    int t   = row & (SEQ - 1);
    const float* xr = x + (size_t)row * DM;
    float cur[8], prv[8];
    float s0 = 0.f, q0 = 0.f, s1 = 0.f, q1 = 0.f;
#pragma unroll
    for (int i = 0; i < 8; i++) {
        int c = threadIdx.x + i * 256;
        float v = xr[c];
        cur[i] = v; s0 += v; q0 += v * v;
        float u = t ? xr[c - DM] : 0.f;
        prv[i] = u; s1 += u; q1 += u * u;
    }
#pragma unroll
    for (int o = 16; o > 0; o >>= 1) {
        s0 += __shfl_xor_sync(0xffffffffu, s0, o);
        q0 += __shfl_xor_sync(0xffffffffu, q0, o);
        s1 += __shfl_xor_sync(0xffffffffu, s1, o);
        q1 += __shfl_xor_sync(0xffffffffu, q1, o);
    }
    __shared__ float rs0[8], rq0[8], rs1[8], rq1[8];
    int w = threadIdx.x >> 5;
    if ((threadIdx.x & 31) == 0) { rs0[w] = s0; rq0[w] = q0; rs1[w] = s1; rq1[w] = q1; }
    __syncthreads();
    s0 = 0.f; q0 = 0.f; s1 = 0.f; q1 = 0.f;
#pragma unroll
    for (int i = 0; i < 8; i++) { s0 += rs0[i]; q0 += rq0[i]; s1 += rs1[i]; q1 += rq1[i]; }
    float mu0  = s0 * (1.f / DM);
    float inv0 = rsqrtf(q0 * (1.f / DM) - mu0 * mu0 + 1e-5f);
    float mu1  = s1 * (1.f / DM);
    float inv1 = rsqrtf(q1 * (1.f / DM) - mu1 * mu1 + 1e-5f);
    bool last = (t == SEQ - 1);
#pragma unroll
    for (int i = 0; i < 8; i++) {
        int c = threadIdx.x + i * 256;
        float yc = (cur[i] - mu0) * inv0 * sc[c] + bi[c];
        float yp = t ? (prv[i] - mu1) * inv1 * sc[c] + bi[c] : 0.f;
        size_t off = (size_t)row * DM + c;
        float mr = tmr[c], mk = tmk[c], mv = tmv[c];
        g_rxh[off] = __float2half(yc * mr + (1.f - mr) * yp);
        g_kxh[off] = __float2half(yc * mk + (1.f - mk) * yp);
        g_vxh[off] = __float2half(yc * mv + (1.f - mv) * yp);
        if (last) xlast[(row >> 11) * DM + c] = yc;
    }
}

// ---------------- 4 weight transposes in one launch (fp16 outputs) --------
__global__ void transpose4_kernel(const float* __restrict__ s0, __half* __restrict__ d0,
                                  const float* __restrict__ s1, __half* __restrict__ d1,
                                  const float* __restrict__ s2, __half* __restrict__ d2,
                                  const float* __restrict__ s3, __half* __restrict__ d3)
{
    const float* src; __half* dst;
    switch (blockIdx.z) {
        case 0:  src = s0; dst = d0; break;
        case 1:  src = s1; dst = d1; break;
        case 2:  src = s2; dst = d2; break;
        default: src = s3; dst = d3; break;
    }
    __shared__ float t[32][33];
    int bx = blockIdx.x * 32, by = blockIdx.y * 32;
#pragma unroll
    for (int i = 0; i < 4; i++)
        t[threadIdx.y + i * 8][threadIdx.x] =
            src[(size_t)(by + threadIdx.y + i * 8) * DM + bx + threadIdx.x];
    __syncthreads();
#pragma unroll
    for (int i = 0; i < 4; i++)
        dst[(size_t)(bx + threadIdx.y + i * 8) * DM + by + threadIdx.x] =
            __float2half(t[threadIdx.x][threadIdx.y + i * 8]);
}

// ---------------- fp16 mma.sync GEMM body (R16 champion layout) -----------
#define HSTRIDE 24                        // halves per smem row (16 data + 8 pad)
#define STG_BYTES (2 * 128 * HSTRIDE * 2) // A tile + B tile per stage = 12288 B

__device__ __forceinline__ void gemm_body(const __half* __restrict__ A,
                                          const __half* __restrict__ Bt,
                                          const float* __restrict__ Add,
                                          float* __restrict__ Out,
                                          __half* __restrict__ OutH,
                                          int bm, int bn)
{
    extern __shared__ char smem[];
    uint32_t sb = smem_u32(smem);
    int tid = threadIdx.x, lane = tid & 31, warp = tid >> 5;
    int r0 = lane >> 2, c0 = lane & 3;
    int wm = (warp >> 2) * 64, wn = (warp & 3) * 32;

    const __half* Ag = A  + (size_t)bm * DM;
    const __half* Bg = Bt + (size_t)bn * DM;

    int lane7 = lane & 7;
    uint32_t a_off = (uint32_t)(((wm + ((lane >> 3) & 1) * 8 + lane7) * HSTRIDE
                                + ((lane >> 4) & 1) * 8) * 2);
    uint32_t b_off = (uint32_t)(((wn + ((lane >> 4) & 1) * 8 + lane7) * HSTRIDE
                                + ((lane >> 3) & 1) * 8) * 2);

    // copy: two threads per row, 16B each (champion mapping)
    int cm = tid >> 1, cq = (tid & 1) * 8;
    auto copy_stage = [&](int buf, int kt) {
        uint32_t sA = sb + buf * STG_BYTES;
        uint32_t sB = sA + 128 * HSTRIDE * 2;
        uint32_t off = cm * (HSTRIDE * 2) + cq * 2;
        cp16(sA + off, Ag + kt * BK + (size_t)cm * DM + cq);
        cp16(sB + off, Bg + kt * BK + (size_t)cm * DM + cq);
        cp_commit();
    };

    float acc[4][4][4];
#pragma unroll
    for (int i = 0; i < 4; i++)
#pragma unroll
        for (int j = 0; j < 4; j++)
#pragma unroll
            for (int e = 0; e < 4; e++) acc[i][j][e] = 0.f;

    copy_stage(0, 0);
    copy_stage(1, 1);
    copy_stage(2, 2);
    cp_wait<1>();
    __syncthreads();

    int buf = 0, cbuf = 3;
    for (int kt = 0; kt < NKT; kt++) {
        if (kt && !(kt & 1)) {
            cp_wait<1>();
            __syncthreads();
        }
        uint32_t sA = sb + buf * STG_BYTES;
        uint32_t sB = sA + 128 * HSTRIDE * 2;
        unsigned af[4][4], bf[8];
#pragma unroll
        for (int i = 0; i < 4; i++)
            ldsm4(af[i], sA + a_off + i * (16 * HSTRIDE * 2));
        ldsm4(&bf[0], sB + b_off);
        ldsm4(&bf[4], sB + b_off + 16 * HSTRIDE * 2);
#pragma unroll
        for (int i = 0; i < 4; i++)
#pragma unroll
            for (int j = 0; j < 4; j++)
                mma_f16(acc[i][j], af[i], &bf[j * 2]);
        if (kt + 3 < NKT) copy_stage(cbuf, kt + 3);
        else              cp_commit();
        buf  = (buf  == STAGES - 1) ? 0 : buf + 1;
        cbuf = (cbuf == STAGES - 1) ? 0 : cbuf + 1;
    }

#pragma unroll
    for (int i = 0; i < 4; i++) {
        int row = bm + wm + i * 16 + r0;
#pragma unroll
        for (int j = 0; j < 4; j++) {
            int col = bn + wn + j * 8 + c0 * 2;
            size_t o0 = (size_t)row * DM + col;
            size_t o1 = (size_t)(row + 8) * DM + col;
            float2 v0 = make_float2(acc[i][j][0], acc[i][j][1]);
            float2 v1 = make_float2(acc[i][j][2], acc[i][j][3]);
            if (Out) {
                float2 a0 = *(const float2*)(Add + o0);
                float2 a1 = *(const float2*)(Add + o1);
                v0.x += a0.x; v0.y += a0.y;
                v1.x += a1.x; v1.y += a1.y;
                *(float2*)(Out + o0) = v0;
                *(float2*)(Out + o1) = v1;
            } else {
                *(__half2*)(OutH + o0) = __floats2half2_rn(v0.x, v0.y);
                *(__half2*)(OutH + o1) = __floats2half2_rn(v1.x, v1.y);
            }
        }
    }
}

// fused r/k/v projections (z selects GEMM; wave order is z-major so weight
// locality per wave is preserved; all 3 weights fit in L2 regardless)
__global__ void __launch_bounds__(256, 2) rkv_gemm_kernel(const __half* __restrict__ wtr,
                                                          const __half* __restrict__ wtk,
                                                          const __half* __restrict__ wtv)
{
    int z = blockIdx.z;
    const __half* A  = (z == 0) ? g_rxh : (z == 1) ? g_kxh : g_vxh;
    const __half* Bt = (z == 0) ? wtr   : (z == 1) ? wtk   : wtv;
    __half* Ch       = (z == 0) ? g_rh  : (z == 1) ? g_kh  : g_vh;
    gemm_body(A, Bt, nullptr, nullptr, Ch, blockIdx.y * 128, blockIdx.x * 128);
}

__global__ void __launch_bounds__(256, 2) out_gemm_kernel(const __half* __restrict__ wto,
                                                          const float* __restrict__ Add,
                                                          float* __restrict__ Out)
{
    gemm_body(g_atth, wto, Add, Out, nullptr, blockIdx.y * 128, blockIdx.x * 128);
}

// ---------------- fused attention + per-chunk kv outer product ------------
#define RSTR 72    // halves per row, r/k/v tiles (64 data + 8 pad)
#define SSTR 136   // halves per row, S tile (128 data + 8 pad)
#define ATT_SMEM (3 * 128 * RSTR * 2 + 128 * SSTR * 2 + 256)   // +wk array

__global__ void __launch_bounds__(256, 2) att_kernel(const float* __restrict__ tdcy,
                                                     const float* __restrict__ tfirst)
{
    int bch = blockIdx.x;
    int h = bch & 31;
    int chunk = (bch >> 5) & 15;
    int b = bch >> 9;
    extern __shared__ char smem[];
    __half* rs = (__half*)smem;
    __half* ks = rs + 128 * RSTR;
    __half* vs = ks + 128 * RSTR;
    __half* ss = vs + 128 * RSTR;
    __half* wkh = ss + 128 * SSTR;     // 128 halves
    int tid = threadIdx.x, lane = tid & 31, warp = tid >> 5;
    int lane7 = lane & 7;
    int r0 = lane >> 2, c0 = lane & 3;

    float logw = -expf(tdcy[h]);
    float u    =  expf(tfirst[h]);

    size_t gbase = ((size_t)(b * SEQ + chunk * CK)) * DM + h * 64;
#pragma unroll
    for (int q = 0; q < 4; q++) {
        int idx = q * 256 + tid;
        int row = idx >> 3, c8 = (idx & 7) * 8;
        size_t off = gbase + (size_t)row * DM + c8;
        *(uint4*)&rs[row * RSTR + c8] = *(const uint4*)(g_rh + off);
        *(uint4*)&ks[row * RSTR + c8] = *(const uint4*)(g_kh + off);
        *(uint4*)&vs[row * RSTR + c8] = *(const uint4*)(g_vh + off);
    }
    if (tid < 128) wkh[tid] = __float2half(expf(logw * (float)(127 - tid)));
    __syncthreads();

    // phase 2: S = r @ k^T
    int wm = (warp >> 2) * 64, wn = (warp & 3) * 32;
    uint32_t rs_b = smem_u32(rs), ks_b = smem_u32(ks);
    uint32_t vs_b = smem_u32(vs), ss_b = smem_u32(ss);
    uint32_t a_off = rs_b + (uint32_t)(((wm + ((lane >> 3) & 1) * 8 + lane7) * RSTR
                                      + ((lane >> 4) & 1) * 8) * 2);
    uint32_t b_off = ks_b + (uint32_t)(((wn + ((lane >> 4) & 1) * 8 + lane7) * RSTR
                                      + ((lane >> 3) & 1) * 8) * 2);
    float acc[4][4][4];
#pragma unroll
    for (int i = 0; i < 4; i++)
#pragma unroll
        for (int j = 0; j < 4; j++)
#pragma unroll
            for (int e = 0; e < 4; e++) acc[i][j][e] = 0.f;
#pragma unroll
    for (int kb = 0; kb < 4; kb++) {
        unsigned af[4][4], bf[8];
#pragma unroll
        for (int i = 0; i < 4; i++)
            ldsm4(af[i], a_off + i * (16 * RSTR * 2) + kb * 32);
        ldsm4(&bf[0], b_off + kb * 32);
        ldsm4(&bf[4], b_off + 16 * RSTR * 2 + kb * 32);
#pragma unroll
        for (int i = 0; i < 4; i++)
#pragma unroll
            for (int j = 0; j < 4; j++)
                mma_f16(acc[i][j], af[i], &bf[j * 2]);
    }

#pragma unroll
    for (int i = 0; i < 4; i++) {
#pragma unroll
        for (int j = 0; j < 4; j++) {
            int ri = wm + i * 16 + r0;
            int cj = wn + j * 8 + c0 * 2;
#pragma unroll
            for (int e = 0; e < 4; e++) {
                int rr = ri + (e >> 1) * 8;
                int cc = cj + (e & 1);
                float m;
                if (rr > cc)       m = expf(logw * (float)(rr - cc - 1));
                else if (rr == cc) m = u;
                else               m = 0.f;
                ss[rr * SSTR + cc] = __float2half(acc[i][j][e] * m);
            }
        }
    }
    __syncthreads();

    // phase 4: sep = S @ v
    int wm2 = (warp >> 2) * 64, wn2 = (warp & 3) * 16;
    uint32_t a2 = ss_b + (uint32_t)(((wm2 + ((lane >> 3) & 1) * 8 + lane7) * SSTR
                                   + ((lane >> 4) & 1) * 8) * 2);
    uint32_t bt = vs_b + (uint32_t)(((((lane >> 3) & 1) * 8 + lane7) * RSTR
                                   + wn2 + ((lane >> 4) & 1) * 8) * 2);
    float acc2[4][2][4];
#pragma unroll
    for (int i = 0; i < 4; i++)
#pragma unroll
        for (int j = 0; j < 2; j++)
#pragma unroll
            for (int e = 0; e < 4; e++) acc2[i][j][e] = 0.f;
#pragma unroll
    for (int kb = 0; kb < 8; kb++) {
        unsigned af[4][4], bf[4];
#pragma unroll
        for (int i = 0; i < 4; i++)
            ldsm4(af[i], a2 + i * (16 * SSTR * 2) + kb * 32);
        ldsm4t(bf, bt + kb * (16 * RSTR * 2));
#pragma unroll
        for (int i = 0; i < 4; i++)
#pragma unroll
            for (int j = 0; j < 2; j++)
                mma_f16(acc2[i][j], af[i], &bf[j * 2]);
    }
#pragma unroll
    for (int i = 0; i < 4; i++) {
        int row = wm2 + i * 16 + r0;
        size_t o = ((size_t)(b * SEQ + chunk * CK + row)) * DM + h * 64;
#pragma unroll
        for (int j = 0; j < 2; j++) {
            int col = wn2 + j * 8 + c0 * 2;
            *(float2*)(g_att + o + col) = make_float2(acc2[i][j][0], acc2[i][j][1]);
            *(float2*)(g_att + o + (size_t)8 * DM + col) = make_float2(acc2[i][j][2], acc2[i][j][3]);
        }
    }

    // phase 5: S2 = (k * w)^T @ v  (M=64 d, N=64 e, K=128 j), tensor cores.
    // A from ks via trans-ldmatrix (bit4->k-block row, bit3->m-block col),
    // scaled per-k by wk fp16 (a0/a1: k=2c..2c+1, a2/a3: +8).
    {
        int wm3 = (warp >> 2) * 32, wn3 = (warp & 3) * 16;
        float acc3[2][2][4];
#pragma unroll
        for (int i = 0; i < 2; i++)
#pragma unroll
            for (int j = 0; j < 2; j++)
#pragma unroll
                for (int e = 0; e < 4; e++) acc3[i][j][e] = 0.f;
#pragma unroll
        for (int kb = 0; kb < 8; kb++) {
            __half2 w2a = *(const __half2*)&wkh[kb * 16 + c0 * 2];
            __half2 w2b = *(const __half2*)&wkh[kb * 16 + c0 * 2 + 8];
            unsigned bf3[4];
            ldsm4t(&bf3[0],
                vs_b + (uint32_t)(((kb * 16 + ((lane >> 3) & 1) * 8 + lane7) * RSTR
                                  + wn3 + ((lane >> 4) & 1) * 8) * 2));
#pragma unroll
            for (int i = 0; i < 2; i++) {
                unsigned af3[4];
                ldsm4t(af3,
                    ks_b + (uint32_t)(((kb * 16 + ((lane >> 4) & 1) * 8 + lane7) * RSTR
                                      + wm3 + i * 16 + ((lane >> 3) & 1) * 8) * 2));
                __half2* ah = (__half2*)af3;
                ah[0] = __hmul2(ah[0], w2a);
                ah[1] = __hmul2(ah[1], w2a);
                ah[2] = __hmul2(ah[2], w2b);
                ah[3] = __hmul2(ah[3], w2b);
#pragma unroll
                for (int j = 0; j < 2; j++)
                    mma_f16(acc3[i][j], af3, &bf3[j * 2]);
            }
        }
        size_t obase = (((size_t)(b * NH + h)) * NC + chunk) * 4096;
#pragma unroll
        for (int i = 0; i < 2; i++) {
            int row = wm3 + i * 16 + r0;
#pragma unroll
            for (int j = 0; j < 2; j++) {
                int col = wn3 + j * 8 + c0 * 2;
                *(float2*)(g_kv + obase + (size_t)row * 64 + col) =
                    make_float2(acc3[i][j][0], acc3[i][j][1]);
                *(float2*)(g_kv + obase + (size_t)(row + 8) * 64 + col) =
                    make_float2(acc3[i][j][2], acc3[i][j][3]);
            }
        }
    }
}

__global__ void combine_kernel(const float* __restrict__ tdcy,
                               float* __restrict__ state_out)
{
    int bh = blockIdx.x;
    int h = bh & 31;
    int tid = threadIdx.x;
    float wC = expf(-expf(tdcy[h]) * 128.f);
    float st[16];
#pragma unroll
    for (int q = 0; q < 16; q++) st[q] = 0.f;
    size_t base = (size_t)bh * NC * 4096;
    for (int c = 0; c < NC; c++) {
        size_t off = base + (size_t)c * 4096;
#pragma unroll
        for (int q = 0; q < 16; q++) {
            size_t idx = off + q * 256 + tid;
            g_state[idx] = st[q];
            st[q] = st[q] * wC + g_kv[idx];
        }
    }
#pragma unroll
    for (int q = 0; q < 16; q++)
        state_out[(size_t)bh * 4096 + q * 256 + tid] = st[q];
}

// ---------------- bias + per-head LN fused (r consumed in fp16) ------------
__global__ void bias_lnx_kernel(const float* __restrict__ tdcy,
                                const float* __restrict__ lsc,
                                const float* __restrict__ lbi)
{
    int c = blockIdx.x, bh = blockIdx.y;
    int h = bh & 31, b = bh >> 5;
    int tid = threadIdx.x;
    __shared__ float rs[64][132];
    __shared__ float ss[64][68];
    {
        int lrow = tid >> 1, lc = (tid & 1) * 32;
        size_t rbase = ((size_t)(b*SEQ + c*CK + lrow)) * DM + h * 64 + lc;
#pragma unroll
        for (int m = 0; m < 4; m++) {
            uint4 raw = *(const uint4*)(g_rh + rbase + m * 8);
            const __half2* rh = (const __half2*)&raw;
#pragma unroll
            for (int e = 0; e < 4; e++) {
                float2 f = __half22float2(rh[e]);
                int d = lc + m * 8 + e * 2;
                rs[d][lrow]     = f.x;
                rs[d + 1][lrow] = f.y;
            }
        }
        size_t sbase = ((size_t)bh * NC + c) * 4096;
#pragma unroll
        for (int q = 0; q < 16; q++) {
            int idx = q * 256 + tid;
            ss[idx >> 6][idx & 63] = g_state[sbase + idx];
        }
    }
    __syncthreads();
    int ty = tid >> 3, tx = tid & 7;
    float acc[4][8] = {};
#pragma unroll 4
    for (int d = 0; d < 64; d++) {
        float4 a  = *(const float4*)&rs[d][ty * 4];
        float4 b0 = *(const float4*)&ss[d][tx * 8];
        float4 b1 = *(const float4*)&ss[d][tx * 8 + 4];
        float ar[4] = {a.x,a.y,a.z,a.w};
        float br[8] = {b0.x,b0.y,b0.z,b0.w,b1.x,b1.y,b1.z,b1.w};
#pragma unroll
        for (int x = 0; x < 4; x++)
#pragma unroll
            for (int e = 0; e < 8; e++)
                acc[x][e] += ar[x] * br[e];
    }
    float logw = -expf(tdcy[h]);
    size_t obase = ((size_t)(b*SEQ + c*CK)) * DM + h * 64;
#pragma unroll
    for (int x = 0; x < 4; x++) {
        int i = ty * 4 + x;
        float wi = expf(logw * (float)i);
        const float* src = g_att + obase + (size_t)i * DM + tx * 8;
        float v[8];
        float4 o0 = *(const float4*)src;
        float4 o1 = *(const float4*)(src + 4);
        v[0] = o0.x + wi * acc[x][0]; v[1] = o0.y + wi * acc[x][1];
        v[2] = o0.z + wi * acc[x][2]; v[3] = o0.w + wi * acc[x][3];
        v[4] = o1.x + wi * acc[x][4]; v[5] = o1.y + wi * acc[x][5];
        v[6] = o1.z + wi * acc[x][6]; v[7] = o1.w + wi * acc[x][7];
        float s = 0.f, q = 0.f;
#pragma unroll
        for (int e = 0; e < 8; e++) { s += v[e]; q += v[e] * v[e]; }
#pragma unroll
        for (int o = 4; o > 0; o >>= 1) {
            s += __shfl_xor_sync(0xffffffffu, s, o);
            q += __shfl_xor_sync(0xffffffffu, q, o);
        }
        float mu  = s * (1.f / 64.f);
        float inv = rsqrtf(q * (1.f / 64.f) - mu * mu + 1e-5f);
        __half2 hv[4];
#pragma unroll
        for (int e = 0; e < 4; e++) {
            int c0i = h * 64 + tx * 8 + e * 2;
            float y0 = (v[e*2]   - mu) * inv * lsc[c0i]     + lbi[c0i];
            float y1 = (v[e*2+1] - mu) * inv * lsc[c0i + 1] + lbi[c0i + 1];
            hv[e] = __floats2half2_rn(y0, y1);
        }
        *(uint4*)(g_atth + obase + (size_t)i * DM + tx * 8) = *(uint4*)hv;
    }
}

// ---------------- launch ----------------
extern "C" void kernel_launch(void* const* d_in, const int* in_sizes, int n_in,
                              void* d_out, int out_size)
{
    const float* inputs = (const float*)d_in[0];
    const float* tmr    = (const float*)d_in[1];
    const float* tmk    = (const float*)d_in[2];
    const float* tmv    = (const float*)d_in[3];
    const float* Wk     = (const float*)d_in[4];
    const float* Wv     = (const float*)d_in[5];
    const float* Wr     = (const float*)d_in[6];
    const float* Wo     = (const float*)d_in[7];
    const float* tdcy   = (const float*)d_in[8];
    const float* tfirst = (const float*)d_in[9];
    const float* ln1s   = (const float*)d_in[10];
    const float* ln1b   = (const float*)d_in[11];
    const float* lnxs   = (const float*)d_in[12];
    const float* lnxb   = (const float*)d_in[13];

    float* out0      = (float*)d_out;
    float* out_xlast = out0 + (size_t)BZ * SEQ * DM;
    float* out_state = out_xlast + (size_t)BZ * DM;

    const int GSMEM = STAGES * STG_BYTES;   // 61440 B
    cudaFuncSetAttribute(rkv_gemm_kernel, cudaFuncAttributeMaxDynamicSharedMemorySize, GSMEM);
    cudaFuncSetAttribute(out_gemm_kernel, cudaFuncAttributeMaxDynamicSharedMemorySize, GSMEM);
    cudaFuncSetAttribute(att_kernel,      cudaFuncAttributeMaxDynamicSharedMemorySize, ATT_SMEM);

    __half* wtr; __half* wtk; __half* wtv; __half* wto;
    cudaGetSymbolAddress((void**)&wtr, g_wtr);
    cudaGetSymbolAddress((void**)&wtk, g_wtk);
    cudaGetSymbolAddress((void**)&wtv, g_wtv);
    cudaGetSymbolAddress((void**)&wto, g_wto);

    transpose4_kernel<<<dim3(64, 64, 4), dim3(32, 8)>>>(Wr, wtr, Wk, wtk, Wv, wtv, Wo, wto);
    lnmix_kernel<<<MROWS, 256>>>(inputs, ln1s, ln1b, tmr, tmk, tmv, out_xlast);

    rkv_gemm_kernel<<<dim3(DM / 128, MROWS / 128, 3), 256, GSMEM>>>(wtr, wtk, wtv);
    att_kernel<<<BZ * NC * NH, 256, ATT_SMEM>>>(tdcy, tfirst);
    combine_kernel<<<BZ * NH, 256>>>(tdcy, out_state);
    bias_lnx_kernel<<<dim3(NC, BZ * NH), 256>>>(tdcy, lnxs, lnxb);
    out_gemm_kernel<<<dim3(DM / 128, MROWS / 128), 256, GSMEM>>>(wto, inputs, out0);
}